// round 2
// baseline (speedup 1.0000x reference)
#include <cuda_runtime.h>
#include <cstdint>
#include <math.h>

// ---------------- problem constants ----------------
#define M_TOK 100352            // 2048 * 49 tokens
#define DIM   384
#define NH    12
#define HD    32
#define NT    49
#define NWIN  64
#define RANK  16
#define QKV_NREAL 1152
#define QKV_NPACK 2304          // interleaved (main,gate)
#define PROJ_NREAL 384
#define PROJ_NPACK 768
#define SCALE_Q 0.17677669529663687f   // 32^-0.5
#define LORA_SC 2.0f

// ---------------- scratch: device globals (allocation is forbidden) ----------------
__device__ float g_Wqkv[QKV_NPACK * DIM];   // row 2n = qkv_w+qkv_res, row 2n+1 = qkv_gate
__device__ float g_Wproj[PROJ_NPACK * DIM];
__device__ float g_bias[NH * NT * NT];      // gathered rel-pos bias [h][i][j]
__device__ float g_T[M_TOK * RANK];         // lora down-projection (reused for qkv & proj)
__device__ float g_Q[M_TOK * DIM];          // [b][h][t][d] : ((b*12+h)*49+t)*32+d (pre-scaled)
__device__ float g_K[M_TOK * DIM];
__device__ float g_V[M_TOK * DIM];
__device__ float g_AO[M_TOK * DIM];         // attention output, [tok][h*32+d]

// ---------------- small helpers ----------------
__device__ __forceinline__ uint32_t f2tf(float f) {
    uint32_t u;
    asm("cvt.rna.tf32.f32 %0, %1;" : "=r"(u) : "f"(f));
    return u;
}
__device__ __forceinline__ void mma_tf32(float* c, const uint32_t* a, uint32_t b0, uint32_t b1) {
    asm volatile(
        "mma.sync.aligned.m16n8k8.row.col.f32.tf32.tf32.f32 "
        "{%0,%1,%2,%3},{%4,%5,%6,%7},{%8,%9},{%0,%1,%2,%3};"
        : "+f"(c[0]), "+f"(c[1]), "+f"(c[2]), "+f"(c[3])
        : "r"(a[0]), "r"(a[1]), "r"(a[2]), "r"(a[3]), "r"(b0), "r"(b1));
}
__device__ __forceinline__ void cp16(void* s, const void* g) {
    uint32_t sa = (uint32_t)__cvta_generic_to_shared(s);
    asm volatile("cp.async.cg.shared.global [%0], [%1], 16;" :: "r"(sa), "l"(g));
}
__device__ __forceinline__ void cp_commit() { asm volatile("cp.async.commit_group;"); }
template <int N>
__device__ __forceinline__ void cp_wait() { asm volatile("cp.async.wait_group %0;" :: "n"(N)); }

// ---------------- prep: fold res into w, interleave gate, gather bias ----------------
__global__ void prep_kernel(const float* __restrict__ qkv_w, const float* __restrict__ qkv_res,
                            const float* __restrict__ qkv_gate,
                            const float* __restrict__ proj_w, const float* __restrict__ proj_res,
                            const float* __restrict__ proj_gate,
                            const float* __restrict__ bias_table, const int* __restrict__ rel_index) {
    int stride = gridDim.x * blockDim.x;
    int tid = blockIdx.x * blockDim.x + threadIdx.x;
    for (int e = tid; e < QKV_NREAL * DIM; e += stride) {
        int n = e / DIM, k = e % DIM;
        g_Wqkv[(2 * n) * DIM + k]     = qkv_w[e] + qkv_res[e];
        g_Wqkv[(2 * n + 1) * DIM + k] = qkv_gate[e];
    }
    for (int e = tid; e < PROJ_NREAL * DIM; e += stride) {
        int n = e / DIM, k = e % DIM;
        g_Wproj[(2 * n) * DIM + k]     = proj_w[e] + proj_res[e];
        g_Wproj[(2 * n + 1) * DIM + k] = proj_gate[e];
    }
    for (int e = tid; e < NH * NT * NT; e += stride) {
        int h = e / (NT * NT);
        int ij = e % (NT * NT);
        g_bias[e] = bias_table[rel_index[ij] * NH + h];
    }
}

// ---------------- lora down: T[m][r] = dot(X[m], down[r]), fp32 ----------------
__global__ void __launch_bounds__(256) lora_down_kernel(const float* __restrict__ X,
                                                        const float* __restrict__ down,
                                                        float* __restrict__ T) {
    __shared__ float xs[16][DIM];
    int m0 = blockIdx.x * 16;
    for (int e = threadIdx.x; e < 16 * DIM; e += 256)
        xs[e / DIM][e % DIM] = X[(long)(m0 + e / DIM) * DIM + e % DIM];
    __syncthreads();
    int ml = threadIdx.x / RANK;
    int r  = threadIdx.x % RANK;
    const float* dr = down + r * DIM;
    float acc = 0.f;
#pragma unroll 8
    for (int k = 0; k < DIM; k++) acc += xs[ml][k] * dr[k];
    T[(long)(m0 + ml) * RANK + r] = acc;
}

// ---------------- fused tf32 GEMM (main+gate interleaved) + sigmoid-gated lora epilogue ----------------
#define BM 128
#define BN 64          // packed columns (32 real outputs)
#define BK 16
#define ASTR 20        // smem row stride (floats); conflict-free for frag reads
#define KT (DIM / BK)  // 24

template <int MODE>  // 0 = qkv (write g_Q/g_K/g_V), 1 = proj (write outp)
__global__ void __launch_bounds__(256, 2) gemm_lora_kernel(
    const float* __restrict__ A, const float* __restrict__ Bp,
    const float* __restrict__ bias, const float* __restrict__ U,
    const float* __restrict__ T, float* __restrict__ outp) {
    __shared__ float As[2][BM * ASTR];
    __shared__ float Bs[2][BN * ASTR];
    __shared__ float Ts[BM * 17];
    __shared__ float Us[32 * 17];

    int tid = threadIdx.x;
    int warp = tid >> 5, lane = tid & 31;
    int g = lane >> 2, t4 = lane & 3;
    int wm = (warp >> 1) * 32;   // 4 warps along M
    int wn = (warp & 1) * 32;    // 2 warps along packed N
    long m0 = (long)blockIdx.y * BM;
    int n0p = blockIdx.x * BN;
    int n0r = n0p >> 1;

    const float* Ag = A + m0 * DIM;
    const float* Bg = Bp + (long)n0p * DIM;

    float acc[2][4][4];
#pragma unroll
    for (int i = 0; i < 2; i++)
#pragma unroll
        for (int j = 0; j < 4; j++)
#pragma unroll
            for (int c = 0; c < 4; c++) acc[i][j][c] = 0.f;

    auto load_tiles = [&](int kt, int buf) {
        int kbase = kt * BK;
#pragma unroll
        for (int q = 0; q < 2; q++) {
            int cid = tid + q * 256;          // 512 A chunks of 16B
            int r = cid >> 2, c = cid & 3;
            cp16(&As[buf][r * ASTR + c * 4], Ag + (long)r * DIM + kbase + c * 4);
        }
        {
            int r = tid >> 2, c = tid & 3;    // 256 B chunks
            cp16(&Bs[buf][r * ASTR + c * 4], Bg + (long)r * DIM + kbase + c * 4);
        }
    };

    load_tiles(0, 0);
    cp_commit();
    int buf = 0;
    for (int kt = 0; kt < KT; kt++) {
        if (kt + 1 < KT) {
            load_tiles(kt + 1, buf ^ 1);
            cp_commit();
            cp_wait<1>();
        } else {
            cp_wait<0>();
        }
        __syncthreads();
        const float* Ab = As[buf];
        const float* Bb = Bs[buf];
#pragma unroll
        for (int ks = 0; ks < 2; ks++) {
            int ko = ks * 8;
            uint32_t af[2][4], bf[4][2];
#pragma unroll
            for (int mi = 0; mi < 2; mi++) {
                int rb = wm + mi * 16 + g;
                af[mi][0] = f2tf(Ab[rb * ASTR + ko + t4]);
                af[mi][1] = f2tf(Ab[(rb + 8) * ASTR + ko + t4]);
                af[mi][2] = f2tf(Ab[rb * ASTR + ko + t4 + 4]);
                af[mi][3] = f2tf(Ab[(rb + 8) * ASTR + ko + t4 + 4]);
            }
#pragma unroll
            for (int ni = 0; ni < 4; ni++) {
                int nb = wn + ni * 8 + g;
                bf[ni][0] = f2tf(Bb[nb * ASTR + ko + t4]);
                bf[ni][1] = f2tf(Bb[nb * ASTR + ko + t4 + 4]);
            }
#pragma unroll
            for (int mi = 0; mi < 2; mi++)
#pragma unroll
                for (int ni = 0; ni < 4; ni++)
                    mma_tf32(acc[mi][ni], af[mi], bf[ni][0], bf[ni][1]);
        }
        __syncthreads();
        buf ^= 1;
    }

    // stage T rows and U rows for the lora epilogue
    for (int e = tid; e < BM * RANK; e += 256) {
        int r = e & 15, mrow = e >> 4;
        Ts[mrow * 17 + r] = T[(m0 + mrow) * RANK + r];
    }
    for (int e = tid; e < 32 * RANK; e += 256) {
        int r = e & 15, nrow = e >> 4;
        Us[nrow * 17 + r] = U[(n0r + nrow) * RANK + r];
    }
    __syncthreads();

#pragma unroll
    for (int mi = 0; mi < 2; mi++) {
#pragma unroll
        for (int rr = 0; rr < 2; rr++) {
            int mlocal = wm + mi * 16 + g + rr * 8;
            long m = m0 + mlocal;
#pragma unroll
            for (int ni = 0; ni < 4; ni++) {
                int nl = (wn >> 1) + ni * 4 + t4;   // local real col 0..31
                int n = n0r + nl;
                float mainv = acc[mi][ni][rr * 2 + 0];
                float gatev = acc[mi][ni][rr * 2 + 1];
                float lora = 0.f;
#pragma unroll
                for (int r = 0; r < RANK; r++) lora += Ts[mlocal * 17 + r] * Us[nl * 17 + r];
                float gsig = 1.f / (1.f + expf(-gatev));
                float val = mainv + bias[n] + gsig * LORA_SC * lora;
                if (MODE == 0) {
                    int s = n / 384;
                    int rem = n % 384;
                    int h = rem >> 5, d = rem & 31;
                    long b = m / NT;
                    int t = (int)(m % NT);
                    long adr = ((b * NH + h) * NT + t) * HD + d;
                    if (s == 0)      g_Q[adr] = val * SCALE_Q;
                    else if (s == 1) g_K[adr] = val;
                    else             g_V[adr] = val;
                } else {
                    outp[m * DIM + n] = val;
                }
            }
        }
    }
}

// ---------------- windowed attention, one block per (b, h) ----------------
__global__ void __launch_bounds__(128) attn_kernel(const float* __restrict__ mask,
                                                   float* __restrict__ AO) {
    __shared__ float sq[NT * 33], sk[NT * 33], sv[NT * 33];
    __shared__ float sp[NT * NT];
    __shared__ float rinv[NT];
    int bh = blockIdx.x;
    int b = bh / NH, h = bh % NH;
    int w = b % NWIN;
    const float* qb = g_Q + (long)bh * NT * HD;
    const float* kb = g_K + (long)bh * NT * HD;
    const float* vb = g_V + (long)bh * NT * HD;
    int tid = threadIdx.x;
    for (int e = tid; e < NT * HD; e += 128) {
        int i = e >> 5, d = e & 31;
        sq[i * 33 + d] = qb[e];
        sk[i * 33 + d] = kb[e];
        sv[i * 33 + d] = vb[e];
    }
    __syncthreads();
    const float* bi = g_bias + h * NT * NT;
    const float* mk = mask + (long)w * NT * NT;
    for (int e = tid; e < NT * NT; e += 128) {
        int i = e / NT, j = e % NT;
        float a = bi[e] + mk[e];
        const float* qi = sq + i * 33;
        const float* kj = sk + j * 33;
#pragma unroll
        for (int d = 0; d < HD; d++) a += qi[d] * kj[d];
        sp[e] = a;
    }
    __syncthreads();
    if (tid < NT) {
        float* row = sp + tid * NT;
        float mx = -1e30f;
        for (int j = 0; j < NT; j++) mx = fmaxf(mx, row[j]);
        float s = 0.f;
        for (int j = 0; j < NT; j++) {
            float p = expf(row[j] - mx);
            row[j] = p;
            s += p;
        }
        rinv[tid] = 1.f / s;
    }
    __syncthreads();
    float* ao = AO + (long)b * NT * DIM + h * HD;
    for (int e = tid; e < NT * HD; e += 128) {
        int i = e >> 5, d = e & 31;
        float a = 0.f;
        const float* pr = sp + i * NT;
#pragma unroll
        for (int j = 0; j < NT; j++) a += pr[j] * sv[j * 33 + d];
        ao[(long)i * DIM + d] = a * rinv[i];
    }
}

// ---------------- launch ----------------
extern "C" void kernel_launch(void* const* d_in, const int* in_sizes, int n_in,
                              void* d_out, int out_size) {
    const float* x          = (const float*)d_in[0];
    const float* mask       = (const float*)d_in[1];
    const float* qkv_w      = (const float*)d_in[2];
    const float* qkv_b      = (const float*)d_in[3];
    const float* qkv_down   = (const float*)d_in[4];
    const float* qkv_up     = (const float*)d_in[5];
    const float* qkv_gate   = (const float*)d_in[6];
    const float* qkv_res    = (const float*)d_in[7];
    const float* proj_w     = (const float*)d_in[8];
    const float* proj_b     = (const float*)d_in[9];
    const float* proj_down  = (const float*)d_in[10];
    const float* proj_up    = (const float*)d_in[11];
    const float* proj_gate  = (const float*)d_in[12];
    const float* proj_res   = (const float*)d_in[13];
    const float* bias_table = (const float*)d_in[14];
    const int*   rel_index  = (const int*)d_in[15];
    float* out = (float*)d_out;

    float *pT, *pAO, *pWq, *pWp;
    cudaGetSymbolAddress((void**)&pT, g_T);
    cudaGetSymbolAddress((void**)&pAO, g_AO);
    cudaGetSymbolAddress((void**)&pWq, g_Wqkv);
    cudaGetSymbolAddress((void**)&pWp, g_Wproj);

    prep_kernel<<<1024, 256>>>(qkv_w, qkv_res, qkv_gate, proj_w, proj_res, proj_gate,
                               bias_table, rel_index);
    lora_down_kernel<<<M_TOK / 16, 256>>>(x, qkv_down, pT);
    dim3 gq(QKV_NPACK / BN, M_TOK / BM);   // (36, 784)
    gemm_lora_kernel<0><<<gq, 256>>>(x, pWq, qkv_b, qkv_up, pT, nullptr);
    attn_kernel<<<2048 * NH, 128>>>(mask, pAO);
    lora_down_kernel<<<M_TOK / 16, 256>>>(pAO, proj_down, pT);
    dim3 gp(PROJ_NPACK / BN, M_TOK / BM);  // (12, 784)
    gemm_lora_kernel<1><<<gp, 256>>>(pAO, pWp, proj_b, proj_up, pT, out);
}

// round 4
// speedup vs baseline: 1.0381x; 1.0381x over previous
#include <cuda_runtime.h>
#include <cstdint>
#include <math.h>

// ---------------- problem constants ----------------
#define M_TOK 100352            // 2048 * 49 tokens
#define DIM   384
#define NH    12
#define HD    32
#define NT    49
#define NWIN  64
#define RANK  16
#define QKV_NPACK 2304          // interleaved (main,gate) rows
#define PROJ_NPACK 768
#define SCALE_Q 0.17677669529663687f

// ---------------- scratch: device globals ----------------
__device__ float g_Wqkv[QKV_NPACK * DIM];   // row 2n = w+res (tf32-rounded), 2n+1 = gate
__device__ float g_Wproj[PROJ_NPACK * DIM];
__device__ float g_bias[NH * NT * NT];
__device__ float g_T[M_TOK * RANK];
__device__ float g_X[M_TOK * DIM];          // tf32-rounded x
__device__ float g_Q[M_TOK * DIM];          // ((b*12+h)*49+t)*32+d, pre-scaled
__device__ float g_K[M_TOK * DIM];
__device__ float g_V[M_TOK * DIM];
__device__ float g_AO[M_TOK * DIM];         // tf32-rounded attention output

// ---------------- helpers ----------------
__device__ __forceinline__ float f2tf_f(float f) {
    uint32_t u;
    asm("cvt.rna.tf32.f32 %0, %1;" : "=r"(u) : "f"(f));
    return __uint_as_float(u);
}
__device__ __forceinline__ void mma_tf32(float* c, const uint32_t* a, uint32_t b0, uint32_t b1) {
    asm volatile(
        "mma.sync.aligned.m16n8k8.row.col.f32.tf32.tf32.f32 "
        "{%0,%1,%2,%3},{%4,%5,%6,%7},{%8,%9},{%0,%1,%2,%3};"
        : "+f"(c[0]), "+f"(c[1]), "+f"(c[2]), "+f"(c[3])
        : "r"(a[0]), "r"(a[1]), "r"(a[2]), "r"(a[3]), "r"(b0), "r"(b1));
}
__device__ __forceinline__ void cp16(void* s, const void* g) {
    uint32_t sa = (uint32_t)__cvta_generic_to_shared(s);
    asm volatile("cp.async.cg.shared.global [%0], [%1], 16;" :: "r"(sa), "l"(g));
}
__device__ __forceinline__ void cp_commit() { asm volatile("cp.async.commit_group;"); }
template <int N>
__device__ __forceinline__ void cp_wait() { asm volatile("cp.async.wait_group %0;" :: "n"(N)); }

// ---------------- prep ----------------
__global__ void prep_kernel(const float* __restrict__ qkv_w, const float* __restrict__ qkv_res,
                            const float* __restrict__ qkv_gate,
                            const float* __restrict__ proj_w, const float* __restrict__ proj_res,
                            const float* __restrict__ proj_gate,
                            const float* __restrict__ bias_table, const int* __restrict__ rel_index) {
    int stride = gridDim.x * blockDim.x;
    int tid = blockIdx.x * blockDim.x + threadIdx.x;
    for (int e = tid; e < (QKV_NPACK / 2) * DIM; e += stride) {
        int n = e / DIM, k = e % DIM;
        g_Wqkv[(2 * n) * DIM + k]     = f2tf_f(qkv_w[e] + qkv_res[e]);
        g_Wqkv[(2 * n + 1) * DIM + k] = f2tf_f(qkv_gate[e]);
    }
    for (int e = tid; e < (PROJ_NPACK / 2) * DIM; e += stride) {
        int n = e / DIM, k = e % DIM;
        g_Wproj[(2 * n) * DIM + k]     = f2tf_f(proj_w[e] + proj_res[e]);
        g_Wproj[(2 * n + 1) * DIM + k] = f2tf_f(proj_gate[e]);
    }
    for (int e = tid; e < NH * NT * NT; e += stride) {
        int h = e / (NT * NT);
        int ij = e % (NT * NT);
        g_bias[e] = bias_table[rel_index[ij] * NH + h];
    }
}

// ---------------- lora down: T = X @ down^T (fp32); optional tf32-rounded copy ----------------
__global__ void __launch_bounds__(256) lora_down_kernel(const float* __restrict__ X,
                                                        const float* __restrict__ down,
                                                        float* __restrict__ T,
                                                        float* __restrict__ Xr) {
    __shared__ float xs[16][DIM];
    long m0 = (long)blockIdx.x * 16;
    for (int e = threadIdx.x; e < 16 * DIM; e += 256)
        xs[e / DIM][e % DIM] = X[m0 * DIM + e];
    __syncthreads();
    if (Xr) {
        for (int e = threadIdx.x; e < 16 * DIM; e += 256)
            Xr[m0 * DIM + e] = f2tf_f(xs[e / DIM][e % DIM]);
    }
    int ml = threadIdx.x / RANK;
    int r = threadIdx.x % RANK;
    const float* dr = down + r * DIM;
    float acc = 0.f;
#pragma unroll 8
    for (int k = 0; k < DIM; k++) acc += xs[ml][k] * dr[k];
    T[(m0 + ml) * RANK + r] = acc;
}

// ---------------- tf32 mma.sync GEMM (main+gate packed) + fused lora epilogue ----------------
#define BM 128
#define BNP 256                 // packed columns (128 real outputs)
#define BK 32
#define NCH (DIM / BK)          // 12
#define ASTR 36                 // floats per smem row (32 + pad)
#define ST_FL (BM * ASTR + BNP * ASTR)   // floats per stage = 4608 + 9216 = 13824

template <int MODE>  // 0 = qkv scatter, 1 = proj write
__global__ void __launch_bounds__(512, 1) gemm_mma_kernel(
    const float* __restrict__ A, const float* __restrict__ Bp,
    const float* __restrict__ bias, const float* __restrict__ U,
    const float* __restrict__ T, float* __restrict__ outp) {
    extern __shared__ float sm[];

    int tid = threadIdx.x;
    int warp = tid >> 5, lane = tid & 31;
    int g = lane >> 2, t4 = lane & 3;
    int wm = (warp >> 3) * 64;        // 2 M-stripes of 64
    int wn = (warp & 7) * 32;         // 8 N-stripes of 32 packed
    long m0 = (long)blockIdx.y * BM;
    int n0p = blockIdx.x * BNP;
    int n0r = n0p >> 1;

    const float* Ag = A + m0 * DIM;
    const float* Bg = Bp + (long)n0p * DIM;

    float acc[4][4][4];
#pragma unroll
    for (int i = 0; i < 4; i++)
#pragma unroll
        for (int j = 0; j < 4; j++)
#pragma unroll
            for (int c = 0; c < 4; c++) acc[i][j][c] = 0.f;

    auto load_chunk = [&](int c, int s) {
        float* As = sm + s * ST_FL;
        float* Bs = As + BM * ASTR;
        int kb = c * BK;
#pragma unroll
        for (int q = 0; q < 2; q++) {          // A: 1024 16B chunks
            int cid = tid + q * 512;
            int r = cid >> 3, cc = cid & 7;
            cp16(&As[r * ASTR + cc * 4], Ag + (long)r * DIM + kb + cc * 4);
        }
#pragma unroll
        for (int q = 0; q < 4; q++) {          // B: 2048 16B chunks
            int cid = tid + q * 512;
            int r = cid >> 3, cc = cid & 7;
            cp16(&Bs[r * ASTR + cc * 4], Bg + (long)r * DIM + kb + cc * 4);
        }
    };

    load_chunk(0, 0);
    cp_commit();
    for (int c = 0; c < NCH; c++) {
        if (c + 1 < NCH) {
            load_chunk(c + 1, (c + 1) & 1);
            cp_commit();
            cp_wait<1>();
        } else {
            cp_wait<0>();
        }
        __syncthreads();
        const float* Ab = sm + (c & 1) * ST_FL;
        const float* Bb = Ab + BM * ASTR;
#pragma unroll
        for (int ks = 0; ks < 4; ks++) {
            int ko = ks * 8;
            uint32_t af[4][4], bf[4][2];
#pragma unroll
            for (int mi = 0; mi < 4; mi++) {
                int rb = wm + mi * 16 + g;
                af[mi][0] = __float_as_uint(Ab[rb * ASTR + ko + t4]);
                af[mi][1] = __float_as_uint(Ab[(rb + 8) * ASTR + ko + t4]);
                af[mi][2] = __float_as_uint(Ab[rb * ASTR + ko + t4 + 4]);
                af[mi][3] = __float_as_uint(Ab[(rb + 8) * ASTR + ko + t4 + 4]);
            }
#pragma unroll
            for (int ni = 0; ni < 4; ni++) {
                int nb = wn + ni * 8 + g;
                bf[ni][0] = __float_as_uint(Bb[nb * ASTR + ko + t4]);
                bf[ni][1] = __float_as_uint(Bb[nb * ASTR + ko + t4 + 4]);
            }
#pragma unroll
            for (int mi = 0; mi < 4; mi++)
#pragma unroll
                for (int ni = 0; ni < 4; ni++)
                    mma_tf32(acc[mi][ni], af[mi], bf[ni][0], bf[ni][1]);
        }
        __syncthreads();
    }

    // -------- epilogue: stage T/U, lora + bias + sigmoid gate, scatter --------
    float* Ts = sm;              // [128][17]
    float* Us = sm + 128 * 17;   // [128][17]
    for (int e = tid; e < BM * RANK; e += 512) {
        int i = e >> 4, r = e & 15;
        Ts[i * 17 + r] = T[(m0 + i) * RANK + r];
    }
    for (int e = tid; e < 128 * RANK; e += 512) {
        int i = e >> 4, r = e & 15;
        Us[i * 17 + r] = U[(n0r + i) * RANK + r];
    }
    __syncthreads();

    float lor[8][4];
#pragma unroll
    for (int i = 0; i < 8; i++)
#pragma unroll
        for (int j = 0; j < 4; j++) lor[i][j] = 0.f;
#pragma unroll
    for (int r = 0; r < RANK; r++) {
        float tv[8], uv[4];
#pragma unroll
        for (int mi = 0; mi < 4; mi++) {
#pragma unroll
            for (int rr = 0; rr < 2; rr++)
                tv[mi * 2 + rr] = Ts[(wm + mi * 16 + g + rr * 8) * 17 + r];
        }
#pragma unroll
        for (int ni = 0; ni < 4; ni++)
            uv[ni] = Us[((wn >> 1) + ni * 4 + t4) * 17 + r];
#pragma unroll
        for (int i = 0; i < 8; i++)
#pragma unroll
            for (int j = 0; j < 4; j++) lor[i][j] += tv[i] * uv[j];
    }

    float bv[4];
#pragma unroll
    for (int ni = 0; ni < 4; ni++) bv[ni] = __ldg(&bias[n0r + (wn >> 1) + ni * 4 + t4]);

#pragma unroll
    for (int mi = 0; mi < 4; mi++) {
#pragma unroll
        for (int rr = 0; rr < 2; rr++) {
            long m = m0 + wm + mi * 16 + g + rr * 8;
            long bb = m / NT;
            int tt = (int)(m % NT);
            long sc0 = bb * (NH * NT * HD) + (long)tt * HD;
#pragma unroll
            for (int ni = 0; ni < 4; ni++) {
                int n = n0r + (wn >> 1) + ni * 4 + t4;
                float mainv = acc[mi][ni][rr * 2 + 0];
                float gatev = acc[mi][ni][rr * 2 + 1];
                float gsig = 1.f / (1.f + __expf(-gatev));
                float val = mainv + bv[ni] + gsig * 2.0f * lor[mi * 2 + rr][ni];
                if (MODE == 0) {
                    int s = n / 384;
                    int rem = n - s * 384;
                    int h = rem >> 5, d = rem & 31;
                    long adr = sc0 + h * (NT * HD) + d;
                    if (s == 0)      g_Q[adr] = val * SCALE_Q;
                    else if (s == 1) g_K[adr] = val;
                    else             g_V[adr] = val;
                } else {
                    outp[m * DIM + n] = val;
                }
            }
        }
    }
}

// ---------------- windowed attention ----------------
#define PAD 36
__global__ void __launch_bounds__(128) attn_kernel(const float* __restrict__ mask,
                                                   float* __restrict__ AO) {
    __shared__ __align__(16) float sq[NT * PAD], sk[NT * PAD], sv[NT * PAD];
    __shared__ float sp[NT * NT];
    __shared__ float rinv[NT];
    int bh = blockIdx.x;
    int b = bh / NH, h = bh % NH;
    int wdw = b % NWIN;
    const float* qb = g_Q + (long)bh * NT * HD;
    const float* kb = g_K + (long)bh * NT * HD;
    const float* vb = g_V + (long)bh * NT * HD;
    int tid = threadIdx.x;
    for (int e = tid; e < NT * HD; e += 128) {
        int i = e >> 5, d = e & 31;
        sq[i * PAD + d] = qb[e];
        sk[i * PAD + d] = kb[e];
        sv[i * PAD + d] = vb[e];
    }
    __syncthreads();
    const float* bi = g_bias + h * NT * NT;
    const float* mk = mask + (long)wdw * NT * NT;
    for (int it = tid; it < NT * 7; it += 128) {
        int i = it / 7, jb = (it % 7) * 7;
        float acc[7];
#pragma unroll
        for (int t = 0; t < 7; t++) acc[t] = bi[i * NT + jb + t] + mk[i * NT + jb + t];
#pragma unroll
        for (int d4 = 0; d4 < 8; d4++) {
            float4 q = *(const float4*)&sq[i * PAD + d4 * 4];
#pragma unroll
            for (int t = 0; t < 7; t++) {
                float4 k = *(const float4*)&sk[(jb + t) * PAD + d4 * 4];
                acc[t] += q.x * k.x + q.y * k.y + q.z * k.z + q.w * k.w;
            }
        }
#pragma unroll
        for (int t = 0; t < 7; t++) sp[i * NT + jb + t] = acc[t];
    }
    __syncthreads();
    {
        int w = tid >> 5, lane = tid & 31;
        for (int r = w; r < NT; r += 4) {
            float v1 = sp[r * NT + lane];
            float v2 = (lane + 32 < NT) ? sp[r * NT + lane + 32] : -1e30f;
            float mx = fmaxf(v1, v2);
#pragma unroll
            for (int o = 16; o > 0; o >>= 1) mx = fmaxf(mx, __shfl_xor_sync(0xffffffffu, mx, o));
            float e1 = __expf(v1 - mx);
            float e2 = (lane + 32 < NT) ? __expf(v2 - mx) : 0.f;
            float s = e1 + e2;
#pragma unroll
            for (int o = 16; o > 0; o >>= 1) s += __shfl_xor_sync(0xffffffffu, s, o);
            sp[r * NT + lane] = e1;
            if (lane + 32 < NT) sp[r * NT + lane + 32] = e2;
            if (lane == 0) rinv[r] = 1.f / s;
        }
    }
    __syncthreads();
    float* ao = AO + (long)b * NT * DIM + h * HD;
    for (int it = tid; it < NT * 8; it += 128) {
        int i = it >> 3, db = (it & 7) * 4;
        float4 a = make_float4(0.f, 0.f, 0.f, 0.f);
        const float* pr = sp + i * NT;
#pragma unroll
        for (int j = 0; j < NT; j++) {
            float p = pr[j];
            float4 v = *(const float4*)&sv[j * PAD + db];
            a.x += p * v.x; a.y += p * v.y; a.z += p * v.z; a.w += p * v.w;
        }
        float ri = rinv[i];
        float4 o = make_float4(f2tf_f(a.x * ri), f2tf_f(a.y * ri), f2tf_f(a.z * ri), f2tf_f(a.w * ri));
        *(float4*)&ao[(long)i * DIM + db] = o;
    }
}

// ---------------- launch ----------------
extern "C" void kernel_launch(void* const* d_in, const int* in_sizes, int n_in,
                              void* d_out, int out_size) {
    const float* x          = (const float*)d_in[0];
    const float* mask       = (const float*)d_in[1];
    const float* qkv_w      = (const float*)d_in[2];
    const float* qkv_b      = (const float*)d_in[3];
    const float* qkv_down   = (const float*)d_in[4];
    const float* qkv_up     = (const float*)d_in[5];
    const float* qkv_gate   = (const float*)d_in[6];
    const float* qkv_res    = (const float*)d_in[7];
    const float* proj_w     = (const float*)d_in[8];
    const float* proj_b     = (const float*)d_in[9];
    const float* proj_down  = (const float*)d_in[10];
    const float* proj_up    = (const float*)d_in[11];
    const float* proj_gate  = (const float*)d_in[12];
    const float* proj_res   = (const float*)d_in[13];
    const float* bias_table = (const float*)d_in[14];
    const int*   rel_index  = (const int*)d_in[15];
    float* out = (float*)d_out;

    float *pT, *pX, *pAO, *pWq, *pWp;
    cudaGetSymbolAddress((void**)&pT, g_T);
    cudaGetSymbolAddress((void**)&pX, g_X);
    cudaGetSymbolAddress((void**)&pAO, g_AO);
    cudaGetSymbolAddress((void**)&pWq, g_Wqkv);
    cudaGetSymbolAddress((void**)&pWp, g_Wproj);

    int smem = 2 * ST_FL * sizeof(float);   // 110592 bytes
    cudaFuncSetAttribute(gemm_mma_kernel<0>, cudaFuncAttributeMaxDynamicSharedMemorySize, smem);
    cudaFuncSetAttribute(gemm_mma_kernel<1>, cudaFuncAttributeMaxDynamicSharedMemorySize, smem);

    prep_kernel<<<1024, 256>>>(qkv_w, qkv_res, qkv_gate, proj_w, proj_res, proj_gate,
                               bias_table, rel_index);
    lora_down_kernel<<<M_TOK / 16, 256>>>(x, qkv_down, pT, pX);
    dim3 gq(QKV_NPACK / BNP, M_TOK / BM);   // (9, 784)
    gemm_mma_kernel<0><<<gq, 512, smem>>>(pX, pWq, qkv_b, qkv_up, pT, nullptr);
    attn_kernel<<<2048 * NH, 128>>>(mask, pAO);
    lora_down_kernel<<<M_TOK / 16, 256>>>(pAO, proj_down, pT, nullptr);
    dim3 gp(PROJ_NPACK / BNP, M_TOK / BM);  // (3, 784)
    gemm_mma_kernel<1><<<gp, 512, smem>>>(pAO, pWp, proj_b, proj_up, pT, out);
}

// round 5
// speedup vs baseline: 1.9012x; 1.8314x over previous
#include <cuda_runtime.h>
#include <cstdint>
#include <math.h>

// ---------------- problem constants ----------------
#define M_TOK 100352            // 2048 * 49 tokens
#define DIM   384
#define NH    12
#define HD    32
#define NT    49
#define NWIN  64
#define RANK  16
#define QKV_NPACK 2304          // interleaved (main,gate) rows
#define PROJ_NPACK 768
#define SCALE_Q 0.17677669529663687f

// ---------------- scratch: device globals ----------------
__device__ float g_Wqkv[QKV_NPACK * DIM];   // row 2n = w+res (tf32-rounded), 2n+1 = gate
__device__ float g_Wproj[PROJ_NPACK * DIM];
__device__ float g_bias[NH * NT * NT];
__device__ float g_T[M_TOK * RANK];
__device__ float g_X[M_TOK * DIM];          // tf32-rounded x
__device__ float g_Q[M_TOK * DIM];          // ((b*12+h)*49+t)*32+d, pre-scaled
__device__ float g_K[M_TOK * DIM];
__device__ float g_V[M_TOK * DIM];
__device__ float g_AO[M_TOK * DIM];         // tf32-rounded attention output

// ---------------- helpers ----------------
__device__ __forceinline__ float f2tf_f(float f) {
    uint32_t u;
    asm("cvt.rna.tf32.f32 %0, %1;" : "=r"(u) : "f"(f));
    return __uint_as_float(u);
}
__device__ __forceinline__ void mma_tf32(float* c, const uint32_t* a, uint32_t b0, uint32_t b1) {
    asm volatile(
        "mma.sync.aligned.m16n8k8.row.col.f32.tf32.tf32.f32 "
        "{%0,%1,%2,%3},{%4,%5,%6,%7},{%8,%9},{%0,%1,%2,%3};"
        : "+f"(c[0]), "+f"(c[1]), "+f"(c[2]), "+f"(c[3])
        : "r"(a[0]), "r"(a[1]), "r"(a[2]), "r"(a[3]), "r"(b0), "r"(b1));
}
__device__ __forceinline__ void cp16(void* s, const void* g) {
    uint32_t sa = (uint32_t)__cvta_generic_to_shared(s);
    asm volatile("cp.async.cg.shared.global [%0], [%1], 16;" :: "r"(sa), "l"(g));
}
__device__ __forceinline__ void cp_commit() { asm volatile("cp.async.commit_group;"); }
template <int N>
__device__ __forceinline__ void cp_wait() { asm volatile("cp.async.wait_group %0;" :: "n"(N)); }

// ---------------- prep ----------------
__global__ void prep_kernel(const float* __restrict__ qkv_w, const float* __restrict__ qkv_res,
                            const float* __restrict__ qkv_gate,
                            const float* __restrict__ proj_w, const float* __restrict__ proj_res,
                            const float* __restrict__ proj_gate,
                            const float* __restrict__ bias_table, const int* __restrict__ rel_index) {
    int stride = gridDim.x * blockDim.x;
    int tid = blockIdx.x * blockDim.x + threadIdx.x;
    for (int e = tid; e < (QKV_NPACK / 2) * DIM; e += stride) {
        int n = e / DIM, k = e % DIM;
        g_Wqkv[(2 * n) * DIM + k]     = f2tf_f(qkv_w[e] + qkv_res[e]);
        g_Wqkv[(2 * n + 1) * DIM + k] = f2tf_f(qkv_gate[e]);
    }
    for (int e = tid; e < (PROJ_NPACK / 2) * DIM; e += stride) {
        int n = e / DIM, k = e % DIM;
        g_Wproj[(2 * n) * DIM + k]     = f2tf_f(proj_w[e] + proj_res[e]);
        g_Wproj[(2 * n + 1) * DIM + k] = f2tf_f(proj_gate[e]);
    }
    for (int e = tid; e < NH * NT * NT; e += stride) {
        int h = e / (NT * NT);
        int ij = e % (NT * NT);
        g_bias[e] = bias_table[rel_index[ij] * NH + h];
    }
}

// ---------------- lora down: T = X @ down^T (fp32); optional tf32-rounded copy ----------------
#define DSTR 385
__global__ void __launch_bounds__(256) lora_down_kernel(const float* __restrict__ X,
                                                        const float* __restrict__ down,
                                                        float* __restrict__ T,
                                                        float* __restrict__ Xr) {
    __shared__ float xs[16][DIM];
    __shared__ float ds[RANK * DSTR];
    long m0 = (long)blockIdx.x * 16;
    for (int e = threadIdx.x; e < 16 * DIM; e += 256)
        xs[e / DIM][e % DIM] = X[m0 * DIM + e];
    for (int e = threadIdx.x; e < RANK * DIM; e += 256)
        ds[(e / DIM) * DSTR + (e % DIM)] = down[e];
    __syncthreads();
    if (Xr) {
        for (int e = threadIdx.x; e < 16 * DIM; e += 256)
            Xr[m0 * DIM + e] = f2tf_f(xs[e / DIM][e % DIM]);
    }
    int ml = threadIdx.x / RANK;
    int r = threadIdx.x % RANK;
    const float* dr = ds + r * DSTR;
    float acc = 0.f;
#pragma unroll 8
    for (int k = 0; k < DIM; k++) acc += xs[ml][k] * dr[k];
    T[(m0 + ml) * RANK + r] = acc;
}

// ---------------- tf32 mma.sync GEMM (main+gate packed) + fused lora epilogue ----------------
#define BM 64
#define BNP 128                 // packed columns (64 real outputs)
#define BK 32
#define NCH (DIM / BK)          // 12
#define ASTR 36                 // floats per smem row (32 + pad)
#define ST_FL ((BM + BNP) * ASTR)        // 6912 floats per stage

template <int MODE>  // 0 = qkv scatter, 1 = proj write
__global__ void __launch_bounds__(256, 3) gemm_mma_kernel(
    const float* __restrict__ A, const float* __restrict__ Bp,
    const float* __restrict__ bias, const float* __restrict__ U,
    const float* __restrict__ T, float* __restrict__ outp) {
    extern __shared__ float sm[];

    int tid = threadIdx.x;
    int warp = tid >> 5, lane = tid & 31;
    int g = lane >> 2, t4 = lane & 3;
    int wm = (warp >> 2) * 32;        // 2 M-stripes of 32
    int wn = (warp & 3) * 32;         // 4 N-stripes of 32 packed
    long m0 = (long)blockIdx.x * BM;
    int n0p = blockIdx.y * BNP;
    int n0r = n0p >> 1;

    const float* Ag = A + m0 * DIM;
    const float* Bg = Bp + (long)n0p * DIM;

    float acc[2][4][4];
#pragma unroll
    for (int i = 0; i < 2; i++)
#pragma unroll
        for (int j = 0; j < 4; j++)
#pragma unroll
            for (int c = 0; c < 4; c++) acc[i][j][c] = 0.f;

    auto load_chunk = [&](int c, int s) {
        float* As = sm + s * ST_FL;
        float* Bs = As + BM * ASTR;
        int kb = c * BK;
#pragma unroll
        for (int q = 0; q < 2; q++) {          // A: 512 16B chunks
            int cid = tid + q * 256;
            int r = cid >> 3, cc = cid & 7;
            cp16(&As[r * ASTR + cc * 4], Ag + (long)r * DIM + kb + cc * 4);
        }
#pragma unroll
        for (int q = 0; q < 4; q++) {          // B: 1024 16B chunks
            int cid = tid + q * 256;
            int r = cid >> 3, cc = cid & 7;
            cp16(&Bs[r * ASTR + cc * 4], Bg + (long)r * DIM + kb + cc * 4);
        }
    };

    load_chunk(0, 0);
    cp_commit();
    for (int c = 0; c < NCH; c++) {
        if (c + 1 < NCH) {
            load_chunk(c + 1, (c + 1) & 1);
            cp_commit();
            cp_wait<1>();
        } else {
            cp_wait<0>();
        }
        __syncthreads();
        const float* Ab = sm + (c & 1) * ST_FL;
        const float* Bb = Ab + BM * ASTR;
#pragma unroll
        for (int ks = 0; ks < 4; ks++) {
            int ko = ks * 8;
            uint32_t af[2][4], bf[4][2];
#pragma unroll
            for (int mi = 0; mi < 2; mi++) {
                int rb = wm + mi * 16 + g;
                af[mi][0] = __float_as_uint(Ab[rb * ASTR + ko + t4]);
                af[mi][1] = __float_as_uint(Ab[(rb + 8) * ASTR + ko + t4]);
                af[mi][2] = __float_as_uint(Ab[rb * ASTR + ko + t4 + 4]);
                af[mi][3] = __float_as_uint(Ab[(rb + 8) * ASTR + ko + t4 + 4]);
            }
#pragma unroll
            for (int ni = 0; ni < 4; ni++) {
                int nb = wn + ni * 8 + g;
                bf[ni][0] = __float_as_uint(Bb[nb * ASTR + ko + t4]);
                bf[ni][1] = __float_as_uint(Bb[nb * ASTR + ko + t4 + 4]);
            }
#pragma unroll
            for (int mi = 0; mi < 2; mi++)
#pragma unroll
                for (int ni = 0; ni < 4; ni++)
                    mma_tf32(acc[mi][ni], af[mi], bf[ni][0], bf[ni][1]);
        }
        __syncthreads();
    }

    // -------- epilogue: stage T/U, lora + bias + sigmoid gate, scatter --------
    float* Ts = sm;              // [64][17]
    float* Us = sm + BM * 17;    // [64][17]
    for (int e = tid; e < BM * RANK; e += 256) {
        int i = e >> 4, r = e & 15;
        Ts[i * 17 + r] = T[(m0 + i) * RANK + r];
    }
    for (int e = tid; e < 64 * RANK; e += 256) {
        int i = e >> 4, r = e & 15;
        Us[i * 17 + r] = U[(n0r + i) * RANK + r];
    }
    __syncthreads();

    float lor[4][4];
#pragma unroll
    for (int i = 0; i < 4; i++)
#pragma unroll
        for (int j = 0; j < 4; j++) lor[i][j] = 0.f;
#pragma unroll
    for (int r = 0; r < RANK; r++) {
        float tv[4], uv[4];
#pragma unroll
        for (int mi = 0; mi < 2; mi++)
#pragma unroll
            for (int rr = 0; rr < 2; rr++)
                tv[mi * 2 + rr] = Ts[(wm + mi * 16 + g + rr * 8) * 17 + r];
#pragma unroll
        for (int ni = 0; ni < 4; ni++)
            uv[ni] = Us[((wn >> 1) + ni * 4 + t4) * 17 + r];
#pragma unroll
        for (int i = 0; i < 4; i++)
#pragma unroll
            for (int j = 0; j < 4; j++) lor[i][j] += tv[i] * uv[j];
    }

    float bv[4];
#pragma unroll
    for (int ni = 0; ni < 4; ni++) bv[ni] = __ldg(&bias[n0r + (wn >> 1) + ni * 4 + t4]);

#pragma unroll
    for (int mi = 0; mi < 2; mi++) {
#pragma unroll
        for (int rr = 0; rr < 2; rr++) {
            long m = m0 + wm + mi * 16 + g + rr * 8;
            long bb = m / NT;
            int tt = (int)(m % NT);
            long sc0 = bb * (NH * NT * HD) + (long)tt * HD;
#pragma unroll
            for (int ni = 0; ni < 4; ni++) {
                int n = n0r + (wn >> 1) + ni * 4 + t4;
                float mainv = acc[mi][ni][rr * 2 + 0];
                float gatev = acc[mi][ni][rr * 2 + 1];
                float gsig = 1.f / (1.f + __expf(-gatev));
                float val = mainv + bv[ni] + gsig * 2.0f * lor[mi * 2 + rr][ni];
                if (MODE == 0) {
                    int s = n / 384;
                    int rem = n - s * 384;
                    int h = rem >> 5, d = rem & 31;
                    long adr = sc0 + h * (NT * HD) + d;
                    if (s == 0)      g_Q[adr] = val * SCALE_Q;
                    else if (s == 1) g_K[adr] = val;
                    else             g_V[adr] = val;
                } else {
                    outp[m * DIM + n] = val;
                }
            }
        }
    }
}

// ---------------- windowed attention ----------------
#define PAD 36
__global__ void __launch_bounds__(128, 6) attn_kernel(const float* __restrict__ mask,
                                                      float* __restrict__ AO) {
    __shared__ __align__(16) float sq[NT * PAD], sk[NT * PAD], sv[NT * PAD];
    __shared__ float sp[NT * NT];
    __shared__ float rinv[NT];
    int bh = blockIdx.x;
    int b = bh / NH, h = bh % NH;
    int wdw = b % NWIN;
    const float* qb = g_Q + (long)bh * NT * HD;
    const float* kb = g_K + (long)bh * NT * HD;
    const float* vb = g_V + (long)bh * NT * HD;
    int tid = threadIdx.x;
    for (int e = tid; e < NT * HD; e += 128) {
        int i = e >> 5, d = e & 31;
        sq[i * PAD + d] = qb[e];
        sk[i * PAD + d] = kb[e];
        sv[i * PAD + d] = vb[e];
    }
    __syncthreads();
    const float* bi = g_bias + h * NT * NT;
    const float* mk = mask + (long)wdw * NT * NT;
    for (int it = tid; it < NT * 7; it += 128) {
        int i = it / 7, jb = (it % 7) * 7;
        float acc[7];
#pragma unroll
        for (int t = 0; t < 7; t++) acc[t] = bi[i * NT + jb + t] + mk[i * NT + jb + t];
#pragma unroll 2
        for (int d4 = 0; d4 < 8; d4++) {
            float4 q = *(const float4*)&sq[i * PAD + d4 * 4];
#pragma unroll
            for (int t = 0; t < 7; t++) {
                float4 k = *(const float4*)&sk[(jb + t) * PAD + d4 * 4];
                acc[t] += q.x * k.x + q.y * k.y + q.z * k.z + q.w * k.w;
            }
        }
#pragma unroll
        for (int t = 0; t < 7; t++) sp[i * NT + jb + t] = acc[t];
    }
    __syncthreads();
    {
        int w = tid >> 5, lane = tid & 31;
        for (int r = w; r < NT; r += 4) {
            float v1 = sp[r * NT + lane];
            float v2 = (lane + 32 < NT) ? sp[r * NT + lane + 32] : -1e30f;
            float mx = fmaxf(v1, v2);
#pragma unroll
            for (int o = 16; o > 0; o >>= 1) mx = fmaxf(mx, __shfl_xor_sync(0xffffffffu, mx, o));
            float e1 = __expf(v1 - mx);
            float e2 = (lane + 32 < NT) ? __expf(v2 - mx) : 0.f;
            float s = e1 + e2;
#pragma unroll
            for (int o = 16; o > 0; o >>= 1) s += __shfl_xor_sync(0xffffffffu, s, o);
            sp[r * NT + lane] = e1;
            if (lane + 32 < NT) sp[r * NT + lane + 32] = e2;
            if (lane == 0) rinv[r] = 1.f / s;
        }
    }
    __syncthreads();
    float* ao = AO + (long)b * NT * DIM + h * HD;
    for (int it = tid; it < NT * 8; it += 128) {
        int i = it >> 3, db = (it & 7) * 4;
        float4 a = make_float4(0.f, 0.f, 0.f, 0.f);
        const float* pr = sp + i * NT;
#pragma unroll 7
        for (int j = 0; j < NT; j++) {
            float p = pr[j];
            float4 v = *(const float4*)&sv[j * PAD + db];
            a.x += p * v.x; a.y += p * v.y; a.z += p * v.z; a.w += p * v.w;
        }
        float ri = rinv[i];
        float4 o = make_float4(f2tf_f(a.x * ri), f2tf_f(a.y * ri), f2tf_f(a.z * ri), f2tf_f(a.w * ri));
        *(float4*)&ao[(long)i * DIM + db] = o;
    }
}

// ---------------- launch ----------------
extern "C" void kernel_launch(void* const* d_in, const int* in_sizes, int n_in,
                              void* d_out, int out_size) {
    const float* x          = (const float*)d_in[0];
    const float* mask       = (const float*)d_in[1];
    const float* qkv_w      = (const float*)d_in[2];
    const float* qkv_b      = (const float*)d_in[3];
    const float* qkv_down   = (const float*)d_in[4];
    const float* qkv_up     = (const float*)d_in[5];
    const float* qkv_gate   = (const float*)d_in[6];
    const float* qkv_res    = (const float*)d_in[7];
    const float* proj_w     = (const float*)d_in[8];
    const float* proj_b     = (const float*)d_in[9];
    const float* proj_down  = (const float*)d_in[10];
    const float* proj_up    = (const float*)d_in[11];
    const float* proj_gate  = (const float*)d_in[12];
    const float* proj_res   = (const float*)d_in[13];
    const float* bias_table = (const float*)d_in[14];
    const int*   rel_index  = (const int*)d_in[15];
    float* out = (float*)d_out;

    float *pT, *pX, *pAO, *pWq, *pWp;
    cudaGetSymbolAddress((void**)&pT, g_T);
    cudaGetSymbolAddress((void**)&pX, g_X);
    cudaGetSymbolAddress((void**)&pAO, g_AO);
    cudaGetSymbolAddress((void**)&pWq, g_Wqkv);
    cudaGetSymbolAddress((void**)&pWp, g_Wproj);

    int smem = 2 * ST_FL * sizeof(float);   // 55296 bytes
    cudaFuncSetAttribute(gemm_mma_kernel<0>, cudaFuncAttributeMaxDynamicSharedMemorySize, smem);
    cudaFuncSetAttribute(gemm_mma_kernel<1>, cudaFuncAttributeMaxDynamicSharedMemorySize, smem);

    prep_kernel<<<1024, 256>>>(qkv_w, qkv_res, qkv_gate, proj_w, proj_res, proj_gate,
                               bias_table, rel_index);
    lora_down_kernel<<<M_TOK / 16, 256>>>(x, qkv_down, pT, pX);
    dim3 gq(M_TOK / BM, QKV_NPACK / BNP);   // (1568, 18)
    gemm_mma_kernel<0><<<gq, 256, smem>>>(pX, pWq, qkv_b, qkv_up, pT, nullptr);
    attn_kernel<<<2048 * NH, 128>>>(mask, pAO);
    lora_down_kernel<<<M_TOK / 16, 256>>>(pAO, proj_down, pT, nullptr);
    dim3 gp(M_TOK / BM, PROJ_NPACK / BNP);  // (1568, 6)
    gemm_mma_kernel<1><<<gp, 256, smem>>>(pAO, pWp, proj_b, proj_up, pT, out);
}

// round 7
// speedup vs baseline: 2.1791x; 1.1462x over previous
#include <cuda_runtime.h>
#include <cstdint>
#include <math.h>

// ---------------- problem constants ----------------
#define M_TOK 100352            // 2048 * 49 tokens
#define DIM   384
#define NH    12
#define HD    32
#define NT    49
#define NWIN  64
#define RANK  16
#define QKV_NPACK 2304          // interleaved (main,gate) rows
#define PROJ_NPACK 768
#define SCALE_Q 0.17677669529663687f
#define NKB   (DIM / 8)         // 48 k-blocks of 8

// Fragment-permuted global layouts:
//  A'[m>>4][k>>3][lane][4] : lane=(m&7)*4+(k&3), inner=(m>>3&1)+2*((k>>2)&1)
//  B'[n>>3][k>>3][lane][2] : lane=(n&7)*4+(k&3), inner=(k>>2)&1
#define A_MB_STRIDE (NKB * 128)   // 6144 floats per 16-row block
#define B_NB_STRIDE (NKB * 64)    // 3072 floats per 8-row block

// ---------------- scratch: device globals ----------------
__device__ float g_Wqkv[QKV_NPACK * DIM];   // B'-permuted packed weights
__device__ float g_Wproj[PROJ_NPACK * DIM];
__device__ float g_bias[NH * NT * NT];
__device__ float g_T[M_TOK * RANK];
__device__ float g_X[M_TOK * DIM];          // A'-permuted tf32-rounded x
__device__ float g_Q[M_TOK * DIM];          // ((b*12+h)*49+t)*32+d, pre-scaled
__device__ float g_K[M_TOK * DIM];
__device__ float g_V[M_TOK * DIM];
__device__ float g_AO[M_TOK * DIM];         // A'-permuted tf32-rounded attn output

// ---------------- helpers ----------------
__device__ __forceinline__ float f2tf_f(float f) {
    uint32_t u;
    asm("cvt.rna.tf32.f32 %0, %1;" : "=r"(u) : "f"(f));
    return __uint_as_float(u);
}
__device__ __forceinline__ void mma_tf32(float* c, const float4& a, float b0, float b1) {
    asm volatile(
        "mma.sync.aligned.m16n8k8.row.col.f32.tf32.tf32.f32 "
        "{%0,%1,%2,%3},{%4,%5,%6,%7},{%8,%9},{%0,%1,%2,%3};"
        : "+f"(c[0]), "+f"(c[1]), "+f"(c[2]), "+f"(c[3])
        : "r"(__float_as_uint(a.x)), "r"(__float_as_uint(a.y)),
          "r"(__float_as_uint(a.z)), "r"(__float_as_uint(a.w)),
          "r"(__float_as_uint(b0)), "r"(__float_as_uint(b1)));
}
__device__ __forceinline__ void cp16(void* s, const void* g) {
    uint32_t sa = (uint32_t)__cvta_generic_to_shared(s);
    asm volatile("cp.async.cg.shared.global [%0], [%1], 16;" :: "r"(sa), "l"(g));
}
__device__ __forceinline__ void cp_commit() { asm volatile("cp.async.commit_group;"); }
template <int N>
__device__ __forceinline__ void cp_wait() { asm volatile("cp.async.wait_group %0;" :: "n"(N)); }

__device__ __forceinline__ long a_perm_off(long m, int k) {
    return ((m >> 4) * NKB + (k >> 3)) * 128
         + (((int)(m & 7)) * 4 + (k & 3)) * 4
         + ((int)((m >> 3) & 1)) + (((k >> 2) & 1) << 1);
}

// ---------------- prep ----------------
__global__ void prep_kernel(const float* __restrict__ qkv_w, const float* __restrict__ qkv_res,
                            const float* __restrict__ qkv_gate,
                            const float* __restrict__ proj_w, const float* __restrict__ proj_res,
                            const float* __restrict__ proj_gate,
                            const float* __restrict__ bias_table, const int* __restrict__ rel_index) {
    int stride = gridDim.x * blockDim.x;
    int tid = blockIdx.x * blockDim.x + threadIdx.x;
    auto boff = [](int np, int k) {
        return (long)((np >> 3) * NKB + (k >> 3)) * 64 + ((np & 7) * 4 + (k & 3)) * 2 + ((k >> 2) & 1);
    };
    for (int e = tid; e < (QKV_NPACK / 2) * DIM; e += stride) {
        int n = e / DIM, k = e % DIM;
        g_Wqkv[boff(2 * n, k)]     = f2tf_f(qkv_w[e] + qkv_res[e]);
        g_Wqkv[boff(2 * n + 1, k)] = f2tf_f(qkv_gate[e]);
    }
    for (int e = tid; e < (PROJ_NPACK / 2) * DIM; e += stride) {
        int n = e / DIM, k = e % DIM;
        g_Wproj[boff(2 * n, k)]     = f2tf_f(proj_w[e] + proj_res[e]);
        g_Wproj[boff(2 * n + 1, k)] = f2tf_f(proj_gate[e]);
    }
    for (int e = tid; e < NH * NT * NT; e += stride) {
        int h = e / (NT * NT);
        int ij = e % (NT * NT);
        g_bias[e] = bias_table[rel_index[ij] * NH + h];
    }
}

// ---------------- lora down: T = X @ down^T (fp32); optional permuted tf32 copy ----------------
// PERM=0: X is row-linear. PERM=1: X is A'-fragment-permuted.
#define DSTR 385
template <int PERM>
__global__ void __launch_bounds__(256) lora_down_kernel(const float* __restrict__ X,
                                                        const float* __restrict__ down,
                                                        float* __restrict__ T,
                                                        float* __restrict__ Xr) {
    __shared__ float xs[16][DIM];
    __shared__ float ds[RANK * DSTR];
    long m0 = (long)blockIdx.x * 16;
    if (PERM == 0) {
        for (int e = threadIdx.x; e < 16 * DIM; e += 256)
            xs[e / DIM][e % DIM] = X[m0 * DIM + e];
    } else {
        const float* Xb = X + (m0 >> 4) * A_MB_STRIDE;
        for (int e = threadIdx.x; e < 16 * DIM; e += 256) {
            // e is the source (permuted) offset within this 16-row block
            int kb = e >> 7;
            int rem = e & 127;
            int lane = rem >> 2, inner = rem & 3;
            int ml = (lane >> 2) + ((inner & 1) << 3);
            int k = kb * 8 + (lane & 3) + ((inner >> 1) << 2);
            xs[ml][k] = Xb[e];
        }
    }
    for (int e = threadIdx.x; e < RANK * DIM; e += 256)
        ds[(e / DIM) * DSTR + (e % DIM)] = down[e];
    __syncthreads();
    if (Xr) {
        for (int e = threadIdx.x; e < 16 * DIM; e += 256) {
            int ml = e / DIM, k = e % DIM;
            Xr[a_perm_off(m0 + ml, k)] = f2tf_f(xs[ml][k]);
        }
    }
    int ml = threadIdx.x / RANK;
    int r = threadIdx.x % RANK;
    const float* dr = ds + r * DSTR;
    float acc = 0.f;
#pragma unroll 8
    for (int k = 0; k < DIM; k++) acc += xs[ml][k] * dr[k];
    T[(m0 + ml) * RANK + r] = acc;
}

// ---------------- tf32 mma.sync GEMM, fragment-permuted operands ----------------
#define BM 64
#define BNP 128                 // packed columns (64 real outputs)
#define BK 32
#define NCH (DIM / BK)          // 12
#define A_ST (BM * BK)          // 2048 floats / stage
#define B_ST (BNP * BK)         // 4096 floats / stage
#define ST_FL (A_ST + B_ST)     // 6144 floats / stage

template <int MODE>  // 0 = qkv scatter, 1 = proj write
__global__ void __launch_bounds__(256, 3) gemm_mma_kernel(
    const float* __restrict__ A, const float* __restrict__ Bp,
    const float* __restrict__ bias, const float* __restrict__ U,
    const float* __restrict__ T, float* __restrict__ outp) {
    extern __shared__ float sm[];

    int tid = threadIdx.x;
    int warp = tid >> 5, lane = tid & 31;
    int g = lane >> 2, t4 = lane & 3;
    int wm = (warp >> 2) * 32;        // 2 M-stripes of 32
    int wn = (warp & 3) * 32;         // 4 N-stripes of 32 packed
    int mb_w = (warp >> 2) * 2;       // A 16-row blocks within tile
    int nb_w = (warp & 3) * 4;        // B 8-row blocks within tile
    long m0 = (long)blockIdx.x * BM;
    long mb0 = m0 >> 4;
    int n0p = blockIdx.y * BNP;
    int nb0 = n0p >> 3;
    int n0r = n0p >> 1;

    float acc[2][4][4];
#pragma unroll
    for (int i = 0; i < 2; i++)
#pragma unroll
        for (int j = 0; j < 4; j++)
#pragma unroll
            for (int c = 0; c < 4; c++) acc[i][j][c] = 0.f;

    auto load_chunk = [&](int c, int s) {
        float* As = sm + s * ST_FL;
        float* Bs = As + A_ST;
        const float* Agc = A + mb0 * A_MB_STRIDE + c * 512;   // 4 kb * 128 floats
        const float* Bgc = Bp + (long)nb0 * B_NB_STRIDE + c * 256;
#pragma unroll
        for (int q = 0; q < 2; q++) {          // A: 512 16B chunks (4 runs of 2KB)
            int cid = tid + q * 256;
            int mb = cid >> 7, r = cid & 127;
            cp16(&As[mb * 512 + r * 4], Agc + (long)mb * A_MB_STRIDE + r * 4);
        }
#pragma unroll
        for (int q = 0; q < 4; q++) {          // B: 1024 16B chunks (16 runs of 1KB)
            int cid = tid + q * 256;
            int nb = cid >> 6, r = cid & 63;
            cp16(&Bs[nb * 256 + r * 4], Bgc + (long)nb * B_NB_STRIDE + r * 4);
        }
    };

    load_chunk(0, 0);
    cp_commit();
    for (int c = 0; c < NCH; c++) {
        if (c + 1 < NCH) {
            load_chunk(c + 1, (c + 1) & 1);
            cp_commit();
            cp_wait<1>();
        } else {
            cp_wait<0>();
        }
        __syncthreads();
        const float* Ab = sm + (c & 1) * ST_FL;
        const float* Bb = Ab + A_ST;
#pragma unroll
        for (int ks = 0; ks < 4; ks++) {
            float4 af[2];
            float2 bf[4];
#pragma unroll
            for (int mi = 0; mi < 2; mi++)
                af[mi] = *(const float4*)&Ab[(((mb_w + mi) << 2) + ks) * 128 + lane * 4];
#pragma unroll
            for (int ni = 0; ni < 4; ni++)
                bf[ni] = *(const float2*)&Bb[(((nb_w + ni) << 2) + ks) * 64 + lane * 2];
#pragma unroll
            for (int mi = 0; mi < 2; mi++)
#pragma unroll
                for (int ni = 0; ni < 4; ni++)
                    mma_tf32(acc[mi][ni], af[mi], bf[ni].x, bf[ni].y);
        }
        __syncthreads();
    }

    // -------- epilogue: stage T/U, lora + bias + sigmoid gate, scatter --------
    float* Ts = sm;              // [64][17]
    float* Us = sm + BM * 17;    // [64][17]
    for (int e = tid; e < BM * RANK; e += 256) {
        int i = e >> 4, r = e & 15;
        Ts[i * 17 + r] = T[(m0 + i) * RANK + r];
    }
    for (int e = tid; e < 64 * RANK; e += 256) {
        int i = e >> 4, r = e & 15;
        Us[i * 17 + r] = U[(n0r + i) * RANK + r];
    }
    __syncthreads();

    float lor[4][4];
#pragma unroll
    for (int i = 0; i < 4; i++)
#pragma unroll
        for (int j = 0; j < 4; j++) lor[i][j] = 0.f;
#pragma unroll
    for (int r = 0; r < RANK; r++) {
        float tv[4], uv[4];
#pragma unroll
        for (int mi = 0; mi < 2; mi++)
#pragma unroll
            for (int rr = 0; rr < 2; rr++)
                tv[mi * 2 + rr] = Ts[(wm + mi * 16 + g + rr * 8) * 17 + r];
#pragma unroll
        for (int ni = 0; ni < 4; ni++)
            uv[ni] = Us[((wn >> 1) + ni * 4 + t4) * 17 + r];
#pragma unroll
        for (int i = 0; i < 4; i++)
#pragma unroll
            for (int j = 0; j < 4; j++) lor[i][j] += tv[i] * uv[j];
    }

    float bv[4];
#pragma unroll
    for (int ni = 0; ni < 4; ni++) bv[ni] = __ldg(&bias[n0r + (wn >> 1) + ni * 4 + t4]);

#pragma unroll
    for (int mi = 0; mi < 2; mi++) {
#pragma unroll
        for (int rr = 0; rr < 2; rr++) {
            long m = m0 + wm + mi * 16 + g + rr * 8;
            long bb = m / NT;
            int tt = (int)(m % NT);
            long sc0 = bb * (NH * NT * HD) + (long)tt * HD;
#pragma unroll
            for (int ni = 0; ni < 4; ni++) {
                int n = n0r + (wn >> 1) + ni * 4 + t4;
                float mainv = acc[mi][ni][rr * 2 + 0];
                float gatev = acc[mi][ni][rr * 2 + 1];
                float gsig = 1.f / (1.f + __expf(-gatev));
                float val = mainv + bv[ni] + gsig * 2.0f * lor[mi * 2 + rr][ni];
                if (MODE == 0) {
                    int s = n / 384;
                    int rem = n - s * 384;
                    int h = rem >> 5, d = rem & 31;
                    long adr = sc0 + h * (NT * HD) + d;
                    if (s == 0)      g_Q[adr] = val * SCALE_Q;
                    else if (s == 1) g_K[adr] = val;
                    else             g_V[adr] = val;
                } else {
                    outp[m * DIM + n] = val;
                }
            }
        }
    }
}

// ---------------- windowed attention ----------------
#define PAD 36
__global__ void __launch_bounds__(128, 6) attn_kernel(const float* __restrict__ mask,
                                                      float* __restrict__ AO) {
    __shared__ __align__(16) float sq[NT * PAD], sk[NT * PAD], sv[NT * PAD];
    __shared__ float sp[NT * NT];
    __shared__ float rinv[NT];
    int bh = blockIdx.x;
    int b = bh / NH, h = bh % NH;
    int wdw = b % NWIN;
    const float* qb = g_Q + (long)bh * NT * HD;
    const float* kb = g_K + (long)bh * NT * HD;
    const float* vb = g_V + (long)bh * NT * HD;
    int tid = threadIdx.x;
    for (int e = tid; e < NT * HD; e += 128) {
        int i = e >> 5, d = e & 31;
        sq[i * PAD + d] = qb[e];
        sk[i * PAD + d] = kb[e];
        sv[i * PAD + d] = vb[e];
    }
    __syncthreads();
    const float* bi = g_bias + h * NT * NT;
    const float* mk = mask + (long)wdw * NT * NT;
    for (int it = tid; it < NT * 7; it += 128) {
        int i = it / 7, jb = (it % 7) * 7;
        float acc[7];
#pragma unroll
        for (int t = 0; t < 7; t++) acc[t] = bi[i * NT + jb + t] + mk[i * NT + jb + t];
#pragma unroll 2
        for (int d4 = 0; d4 < 8; d4++) {
            float4 q = *(const float4*)&sq[i * PAD + d4 * 4];
#pragma unroll
            for (int t = 0; t < 7; t++) {
                float4 k = *(const float4*)&sk[(jb + t) * PAD + d4 * 4];
                acc[t] += q.x * k.x + q.y * k.y + q.z * k.z + q.w * k.w;
            }
        }
#pragma unroll
        for (int t = 0; t < 7; t++) sp[i * NT + jb + t] = acc[t];
    }
    __syncthreads();
    {
        int w = tid >> 5, lane = tid & 31;
        for (int r = w; r < NT; r += 4) {
            float v1 = sp[r * NT + lane];
            float v2 = (lane + 32 < NT) ? sp[r * NT + lane + 32] : -1e30f;
            float mx = fmaxf(v1, v2);
#pragma unroll
            for (int o = 16; o > 0; o >>= 1) mx = fmaxf(mx, __shfl_xor_sync(0xffffffffu, mx, o));
            float e1 = __expf(v1 - mx);
            float e2 = (lane + 32 < NT) ? __expf(v2 - mx) : 0.f;
            float s = e1 + e2;
#pragma unroll
            for (int o = 16; o > 0; o >>= 1) s += __shfl_xor_sync(0xffffffffu, s, o);
            sp[r * NT + lane] = e1;
            if (lane + 32 < NT) sp[r * NT + lane + 32] = e2;
            if (lane == 0) rinv[r] = 1.f / s;
        }
    }
    __syncthreads();
    for (int it = tid; it < NT * 8; it += 128) {
        int i = it >> 3, db = (it & 7) * 4;
        float4 a = make_float4(0.f, 0.f, 0.f, 0.f);
        const float* pr = sp + i * NT;
#pragma unroll 7
        for (int j = 0; j < NT; j++) {
            float p = pr[j];
            float4 v = *(const float4*)&sv[j * PAD + db];
            a.x += p * v.x; a.y += p * v.y; a.z += p * v.z; a.w += p * v.w;
        }
        float ri = rinv[i];
        long m = (long)b * NT + i;
        int k = h * HD + db;
        long off = a_perm_off(m, k);   // 4 consecutive k -> lane+0..3 -> stride 4 floats
        AO[off + 0]  = f2tf_f(a.x * ri);
        AO[off + 4]  = f2tf_f(a.y * ri);
        AO[off + 8]  = f2tf_f(a.z * ri);
        AO[off + 12] = f2tf_f(a.w * ri);
    }
}

// ---------------- launch ----------------
extern "C" void kernel_launch(void* const* d_in, const int* in_sizes, int n_in,
                              void* d_out, int out_size) {
    const float* x          = (const float*)d_in[0];
    const float* mask       = (const float*)d_in[1];
    const float* qkv_w      = (const float*)d_in[2];
    const float* qkv_b      = (const float*)d_in[3];
    const float* qkv_down   = (const float*)d_in[4];
    const float* qkv_up     = (const float*)d_in[5];
    const float* qkv_gate   = (const float*)d_in[6];
    const float* qkv_res    = (const float*)d_in[7];
    const float* proj_w     = (const float*)d_in[8];
    const float* proj_b     = (const float*)d_in[9];
    const float* proj_down  = (const float*)d_in[10];
    const float* proj_up    = (const float*)d_in[11];
    const float* proj_gate  = (const float*)d_in[12];
    const float* proj_res   = (const float*)d_in[13];
    const float* bias_table = (const float*)d_in[14];
    const int*   rel_index  = (const int*)d_in[15];
    float* out = (float*)d_out;

    float *pT, *pX, *pAO, *pWq, *pWp;
    cudaGetSymbolAddress((void**)&pT, g_T);
    cudaGetSymbolAddress((void**)&pX, g_X);
    cudaGetSymbolAddress((void**)&pAO, g_AO);
    cudaGetSymbolAddress((void**)&pWq, g_Wqkv);
    cudaGetSymbolAddress((void**)&pWp, g_Wproj);

    int smem = 2 * ST_FL * sizeof(float);   // 49152 bytes
    cudaFuncSetAttribute(gemm_mma_kernel<0>, cudaFuncAttributeMaxDynamicSharedMemorySize, smem);
    cudaFuncSetAttribute(gemm_mma_kernel<1>, cudaFuncAttributeMaxDynamicSharedMemorySize, smem);

    prep_kernel<<<1024, 256>>>(qkv_w, qkv_res, qkv_gate, proj_w, proj_res, proj_gate,
                               bias_table, rel_index);
    lora_down_kernel<0><<<M_TOK / 16, 256>>>(x, qkv_down, pT, pX);
    dim3 gq(M_TOK / BM, QKV_NPACK / BNP);   // (1568, 18)
    gemm_mma_kernel<0><<<gq, 256, smem>>>(pX, pWq, qkv_b, qkv_up, pT, nullptr);
    attn_kernel<<<2048 * NH, 128>>>(mask, pAO);
    lora_down_kernel<1><<<M_TOK / 16, 256>>>(pAO, proj_down, pT, nullptr);
    dim3 gp(M_TOK / BM, PROJ_NPACK / BNP);  // (1568, 6)
    gemm_mma_kernel<1><<<gp, 256, smem>>>(pAO, pWp, proj_b, proj_up, pT, out);
}

// round 8
// speedup vs baseline: 2.4055x; 1.1039x over previous
#include <cuda_runtime.h>
#include <cstdint>
#include <math.h>

// ---------------- problem constants ----------------
#define M_TOK 100352            // 2048 * 49 tokens
#define DIM   384
#define NH    12
#define HD    32
#define NT    49
#define NWIN  64
#define RANK  16
#define QKV_NPACK 2304          // interleaved (main,gate) rows
#define PROJ_NPACK 768
#define SCALE_Q 0.17677669529663687f
#define NKB   (DIM / 8)         // 48 k-blocks of 8

// Fragment-permuted global layouts:
//  A'[m>>4][k>>3][lane][4] : lane=(m&7)*4+(k&3), inner=(m>>3&1)+2*((k>>2)&1)
//  B'[n>>3][k>>3][lane][2] : lane=(n&7)*4+(k&3), inner=(k>>2)&1
#define A_MB_STRIDE (NKB * 128)   // 6144 floats per 16-row block
#define B_NB_STRIDE (NKB * 64)    // 3072 floats per 8-row block

// ---------------- scratch: device globals ----------------
__device__ float g_Wqkv[QKV_NPACK * DIM];   // B'-permuted packed weights
__device__ float g_Wproj[PROJ_NPACK * DIM];
__device__ float g_bias[NH * NT * NT];
__device__ float g_T[M_TOK * RANK];
__device__ float g_X[M_TOK * DIM];          // A'-permuted tf32-rounded x
__device__ float g_Q[M_TOK * DIM];          // ((b*12+h)*49+t)*32+d, pre-scaled, tf32-rounded
__device__ float g_K[M_TOK * DIM];
__device__ float g_V[M_TOK * DIM];
__device__ float g_AO[M_TOK * DIM];         // A'-permuted tf32-rounded attn output

// ---------------- helpers ----------------
__device__ __forceinline__ float f2tf_f(float f) {
    uint32_t u;
    asm("cvt.rna.tf32.f32 %0, %1;" : "=r"(u) : "f"(f));
    return __uint_as_float(u);
}
__device__ __forceinline__ void mma_tf32(float* c, const float4& a, float b0, float b1) {
    asm volatile(
        "mma.sync.aligned.m16n8k8.row.col.f32.tf32.tf32.f32 "
        "{%0,%1,%2,%3},{%4,%5,%6,%7},{%8,%9},{%0,%1,%2,%3};"
        : "+f"(c[0]), "+f"(c[1]), "+f"(c[2]), "+f"(c[3])
        : "r"(__float_as_uint(a.x)), "r"(__float_as_uint(a.y)),
          "r"(__float_as_uint(a.z)), "r"(__float_as_uint(a.w)),
          "r"(__float_as_uint(b0)), "r"(__float_as_uint(b1)));
}
__device__ __forceinline__ void cp16(void* s, const void* g) {
    uint32_t sa = (uint32_t)__cvta_generic_to_shared(s);
    asm volatile("cp.async.cg.shared.global [%0], [%1], 16;" :: "r"(sa), "l"(g));
}
__device__ __forceinline__ void cp_commit() { asm volatile("cp.async.commit_group;"); }
template <int N>
__device__ __forceinline__ void cp_wait() { asm volatile("cp.async.wait_group %0;" :: "n"(N)); }

__device__ __forceinline__ long a_perm_off(long m, int k) {
    return ((m >> 4) * NKB + (k >> 3)) * 128
         + (((int)(m & 7)) * 4 + (k & 3)) * 4
         + ((int)((m >> 3) & 1)) + (((k >> 2) & 1) << 1);
}

// ---------------- prep ----------------
__global__ void prep_kernel(const float* __restrict__ qkv_w, const float* __restrict__ qkv_res,
                            const float* __restrict__ qkv_gate,
                            const float* __restrict__ proj_w, const float* __restrict__ proj_res,
                            const float* __restrict__ proj_gate,
                            const float* __restrict__ bias_table, const int* __restrict__ rel_index) {
    int stride = gridDim.x * blockDim.x;
    int tid = blockIdx.x * blockDim.x + threadIdx.x;
    auto boff = [](int np, int k) {
        return (long)((np >> 3) * NKB + (k >> 3)) * 64 + ((np & 7) * 4 + (k & 3)) * 2 + ((k >> 2) & 1);
    };
    for (int e = tid; e < (QKV_NPACK / 2) * DIM; e += stride) {
        int n = e / DIM, k = e % DIM;
        g_Wqkv[boff(2 * n, k)]     = f2tf_f(qkv_w[e] + qkv_res[e]);
        g_Wqkv[boff(2 * n + 1, k)] = f2tf_f(qkv_gate[e]);
    }
    for (int e = tid; e < (PROJ_NPACK / 2) * DIM; e += stride) {
        int n = e / DIM, k = e % DIM;
        g_Wproj[boff(2 * n, k)]     = f2tf_f(proj_w[e] + proj_res[e]);
        g_Wproj[boff(2 * n + 1, k)] = f2tf_f(proj_gate[e]);
    }
    for (int e = tid; e < NH * NT * NT; e += stride) {
        int h = e / (NT * NT);
        int ij = e % (NT * NT);
        g_bias[e] = bias_table[rel_index[ij] * NH + h];
    }
}

// ---------------- lora down: T = X @ down^T (fp32); optional permuted tf32 copy ----------------
// PERM=0: X is row-linear. PERM=1: X is A'-fragment-permuted.
#define DSTR 385
template <int PERM>
__global__ void __launch_bounds__(256) lora_down_kernel(const float* __restrict__ X,
                                                        const float* __restrict__ down,
                                                        float* __restrict__ T,
                                                        float* __restrict__ Xr) {
    __shared__ float xs[16][DIM];
    __shared__ float ds[RANK * DSTR];
    long m0 = (long)blockIdx.x * 16;
    if (PERM == 0) {
        for (int e = threadIdx.x; e < 16 * DIM; e += 256)
            xs[e / DIM][e % DIM] = X[m0 * DIM + e];
    } else {
        const float* Xb = X + (m0 >> 4) * A_MB_STRIDE;
        for (int e = threadIdx.x; e < 16 * DIM; e += 256) {
            int kb = e >> 7;
            int rem = e & 127;
            int lane = rem >> 2, inner = rem & 3;
            int ml = (lane >> 2) + ((inner & 1) << 3);
            int k = kb * 8 + (lane & 3) + ((inner >> 1) << 2);
            xs[ml][k] = Xb[e];
        }
    }
    for (int e = threadIdx.x; e < RANK * DIM; e += 256)
        ds[(e / DIM) * DSTR + (e % DIM)] = down[e];
    __syncthreads();
    if (Xr) {
        for (int e = threadIdx.x; e < 16 * DIM; e += 256) {
            int ml = e / DIM, k = e % DIM;
            Xr[a_perm_off(m0 + ml, k)] = f2tf_f(xs[ml][k]);
        }
    }
    int ml = threadIdx.x / RANK;
    int r = threadIdx.x % RANK;
    const float* dr = ds + r * DSTR;
    float acc = 0.f;
#pragma unroll 8
    for (int k = 0; k < DIM; k++) acc += xs[ml][k] * dr[k];
    T[(m0 + ml) * RANK + r] = acc;
}

// ---------------- tf32 mma.sync GEMM, fragment-permuted operands ----------------
#define BM 64
#define BNP 128                 // packed columns (64 real outputs)
#define BK 32
#define NCH (DIM / BK)          // 12
#define A_ST (BM * BK)          // 2048 floats / stage
#define B_ST (BNP * BK)         // 4096 floats / stage
#define ST_FL (A_ST + B_ST)     // 6144 floats / stage

template <int MODE>  // 0 = qkv scatter, 1 = proj write
__global__ void __launch_bounds__(256, 3) gemm_mma_kernel(
    const float* __restrict__ A, const float* __restrict__ Bp,
    const float* __restrict__ bias, const float* __restrict__ U,
    const float* __restrict__ T, float* __restrict__ outp) {
    extern __shared__ float sm[];

    int tid = threadIdx.x;
    int warp = tid >> 5, lane = tid & 31;
    int g = lane >> 2, t4 = lane & 3;
    int wm = (warp >> 2) * 32;        // 2 M-stripes of 32
    int wn = (warp & 3) * 32;         // 4 N-stripes of 32 packed
    int mb_w = (warp >> 2) * 2;       // A 16-row blocks within tile
    int nb_w = (warp & 3) * 4;        // B 8-row blocks within tile
    long m0 = (long)blockIdx.x * BM;
    long mb0 = m0 >> 4;
    int n0p = blockIdx.y * BNP;
    int nb0 = n0p >> 3;
    int n0r = n0p >> 1;

    float acc[2][4][4];
#pragma unroll
    for (int i = 0; i < 2; i++)
#pragma unroll
        for (int j = 0; j < 4; j++)
#pragma unroll
            for (int c = 0; c < 4; c++) acc[i][j][c] = 0.f;

    auto load_chunk = [&](int c, int s) {
        float* As = sm + s * ST_FL;
        float* Bs = As + A_ST;
        const float* Agc = A + mb0 * A_MB_STRIDE + c * 512;   // 4 kb * 128 floats
        const float* Bgc = Bp + (long)nb0 * B_NB_STRIDE + c * 256;
#pragma unroll
        for (int q = 0; q < 2; q++) {          // A: 512 16B chunks (4 runs of 2KB)
            int cid = tid + q * 256;
            int mb = cid >> 7, r = cid & 127;
            cp16(&As[mb * 512 + r * 4], Agc + (long)mb * A_MB_STRIDE + r * 4);
        }
#pragma unroll
        for (int q = 0; q < 4; q++) {          // B: 1024 16B chunks (16 runs of 1KB)
            int cid = tid + q * 256;
            int nb = cid >> 6, r = cid & 63;
            cp16(&Bs[nb * 256 + r * 4], Bgc + (long)nb * B_NB_STRIDE + r * 4);
        }
    };

    load_chunk(0, 0);
    cp_commit();
    for (int c = 0; c < NCH; c++) {
        if (c + 1 < NCH) {
            load_chunk(c + 1, (c + 1) & 1);
            cp_commit();
            cp_wait<1>();
        } else {
            cp_wait<0>();
        }
        __syncthreads();
        const float* Ab = sm + (c & 1) * ST_FL;
        const float* Bb = Ab + A_ST;
#pragma unroll
        for (int ks = 0; ks < 4; ks++) {
            float4 af[2];
            float2 bf[4];
#pragma unroll
            for (int mi = 0; mi < 2; mi++)
                af[mi] = *(const float4*)&Ab[(((mb_w + mi) << 2) + ks) * 128 + lane * 4];
#pragma unroll
            for (int ni = 0; ni < 4; ni++)
                bf[ni] = *(const float2*)&Bb[(((nb_w + ni) << 2) + ks) * 64 + lane * 2];
#pragma unroll
            for (int mi = 0; mi < 2; mi++)
#pragma unroll
                for (int ni = 0; ni < 4; ni++)
                    mma_tf32(acc[mi][ni], af[mi], bf[ni].x, bf[ni].y);
        }
        __syncthreads();
    }

    // -------- epilogue: stage T/U, lora + bias + sigmoid gate, scatter --------
    float* Ts = sm;              // [64][17]
    float* Us = sm + BM * 17;    // [64][17]
    for (int e = tid; e < BM * RANK; e += 256) {
        int i = e >> 4, r = e & 15;
        Ts[i * 17 + r] = T[(m0 + i) * RANK + r];
    }
    for (int e = tid; e < 64 * RANK; e += 256) {
        int i = e >> 4, r = e & 15;
        Us[i * 17 + r] = U[(n0r + i) * RANK + r];
    }
    __syncthreads();

    float lor[4][4];
#pragma unroll
    for (int i = 0; i < 4; i++)
#pragma unroll
        for (int j = 0; j < 4; j++) lor[i][j] = 0.f;
#pragma unroll
    for (int r = 0; r < RANK; r++) {
        float tv[4], uv[4];
#pragma unroll
        for (int mi = 0; mi < 2; mi++)
#pragma unroll
            for (int rr = 0; rr < 2; rr++)
                tv[mi * 2 + rr] = Ts[(wm + mi * 16 + g + rr * 8) * 17 + r];
#pragma unroll
        for (int ni = 0; ni < 4; ni++)
            uv[ni] = Us[((wn >> 1) + ni * 4 + t4) * 17 + r];
#pragma unroll
        for (int i = 0; i < 4; i++)
#pragma unroll
            for (int j = 0; j < 4; j++) lor[i][j] += tv[i] * uv[j];
    }

    float bv[4];
#pragma unroll
    for (int ni = 0; ni < 4; ni++) bv[ni] = __ldg(&bias[n0r + (wn >> 1) + ni * 4 + t4]);

#pragma unroll
    for (int mi = 0; mi < 2; mi++) {
#pragma unroll
        for (int rr = 0; rr < 2; rr++) {
            long m = m0 + wm + mi * 16 + g + rr * 8;
            long bb = m / NT;
            int tt = (int)(m % NT);
            long sc0 = bb * (NH * NT * HD) + (long)tt * HD;
#pragma unroll
            for (int ni = 0; ni < 4; ni++) {
                int n = n0r + (wn >> 1) + ni * 4 + t4;
                float mainv = acc[mi][ni][rr * 2 + 0];
                float gatev = acc[mi][ni][rr * 2 + 1];
                float gsig = 1.f / (1.f + __expf(-gatev));
                float val = mainv + bv[ni] + gsig * 2.0f * lor[mi * 2 + rr][ni];
                if (MODE == 0) {
                    int s = n / 384;
                    int rem = n - s * 384;
                    int h = rem >> 5, d = rem & 31;
                    long adr = sc0 + h * (NT * HD) + d;
                    if (s == 0)      g_Q[adr] = f2tf_f(val * SCALE_Q);
                    else if (s == 1) g_K[adr] = f2tf_f(val);
                    else             g_V[adr] = f2tf_f(val);
                } else {
                    outp[m * DIM + n] = val;
                }
            }
        }
    }
}

// ---------------- windowed attention, tensor-core version ----------------
// One block per (b,h). 4 warps = 4 m-blocks of 16 rows (49 -> 64 padded).
// QK^T: M=64, N=56 (49 padded, masked -1e30), K=32.  PV: M=64, K=56, N=32.
#define SPS 58
__global__ void __launch_bounds__(128, 6) attn_kernel(const float* __restrict__ mask,
                                                      float* __restrict__ AO) {
    __shared__ __align__(16) float qs[4 * 4 * 128];   // A-frags Q  [mb][kb][lane][4]
    __shared__ __align__(16) float ks[7 * 4 * 64];    // B-frags K  [nb][kb][lane][2]
    __shared__ __align__(16) float vs[7 * 4 * 64];    // B-frags V  [kb2][nb][lane][2]
    __shared__ __align__(16) float sp[64 * SPS];      // bias+mask, then P
    __shared__ float rinv[64];
    int bh = blockIdx.x;
    int b = bh / NH, h = bh % NH;
    int wdw = b % NWIN;
    int tid = threadIdx.x;
    int warp = tid >> 5, lane = tid & 31, g = lane >> 2, t4 = lane & 3;

    // phase 1: zero frag buffers (padding), init score board to -1e30
    for (int e = tid; e < 2048; e += 128) qs[e] = 0.f;
    for (int e = tid; e < 1792; e += 128) { ks[e] = 0.f; vs[e] = 0.f; }
    for (int e = tid; e < 64 * SPS; e += 128) sp[e] = -1e30f;
    __syncthreads();

    // phase 2: scatter Q,K,V into fragment layouts; fill bias+mask
    const float* qb = g_Q + (long)bh * NT * HD;
    const float* kg = g_K + (long)bh * NT * HD;
    const float* vg = g_V + (long)bh * NT * HD;
    for (int e = tid; e < NT * HD; e += 128) {
        int t = e >> 5, d = e & 31;
        int dkb = d >> 3, dr = d & 7, dt4 = dr & 3, dhi = dr >> 2;
        // Q as A-frag: row t, col d
        int mb = t >> 4, r = t & 15;
        qs[(((mb << 2) + dkb) * 32 + ((r & 7) << 2) + dt4) * 4 + (r >> 3) + 2 * dhi] = qb[e];
        // K as B-frag: n = t, k = d
        int knb = t >> 3, jr = t & 7;
        ks[(((knb << 2) + dkb) * 32 + (jr << 2) + dt4) * 2 + dhi] = kg[e];
        // V as B-frag for PV: k = t, n = d
        int vkb = t >> 3, tr = t & 7;
        vs[(((vkb << 2) + (d >> 3)) * 32 + ((d & 7) << 2) + (tr & 3)) * 2 + (tr >> 2)] = vg[e];
    }
    const float* bi = g_bias + h * NT * NT;
    const float* mk = mask + (long)wdw * NT * NT;
    for (int e = tid; e < NT * NT; e += 128) {
        int i = e / NT, j = e - i * NT;
        sp[i * SPS + j] = bi[e] + mk[e];
    }
    __syncthreads();

    // phase 3: QK^T with bias+mask as accumulator init
    int base = (warp * 16 + g) * SPS;
    int base2 = base + 8 * SPS;
    float acc[7][4];
#pragma unroll
    for (int nb = 0; nb < 7; nb++) {
        float2 x = *(const float2*)&sp[base + nb * 8 + 2 * t4];
        float2 y = *(const float2*)&sp[base2 + nb * 8 + 2 * t4];
        acc[nb][0] = x.x; acc[nb][1] = x.y; acc[nb][2] = y.x; acc[nb][3] = y.y;
    }
#pragma unroll
    for (int kb = 0; kb < 4; kb++) {
        float4 a = *(const float4*)&qs[(((warp << 2) + kb) * 32 + lane) * 4];
#pragma unroll
        for (int nb = 0; nb < 7; nb++) {
            float2 bv = *(const float2*)&ks[(((nb << 2) + kb) * 32 + lane) * 2];
            mma_tf32(acc[nb], a, bv.x, bv.y);
        }
    }

    // softmax in fragments: rows (warp*16+g) and (+8); each row spread over 4 t4-lanes
    float mx1 = -1e30f, mx2 = -1e30f;
#pragma unroll
    for (int nb = 0; nb < 7; nb++) {
        mx1 = fmaxf(mx1, fmaxf(acc[nb][0], acc[nb][1]));
        mx2 = fmaxf(mx2, fmaxf(acc[nb][2], acc[nb][3]));
    }
    mx1 = fmaxf(mx1, __shfl_xor_sync(0xffffffffu, mx1, 1));
    mx1 = fmaxf(mx1, __shfl_xor_sync(0xffffffffu, mx1, 2));
    mx2 = fmaxf(mx2, __shfl_xor_sync(0xffffffffu, mx2, 1));
    mx2 = fmaxf(mx2, __shfl_xor_sync(0xffffffffu, mx2, 2));
    float s1 = 0.f, s2 = 0.f;
#pragma unroll
    for (int nb = 0; nb < 7; nb++) {
        acc[nb][0] = __expf(acc[nb][0] - mx1);
        acc[nb][1] = __expf(acc[nb][1] - mx1);
        acc[nb][2] = __expf(acc[nb][2] - mx2);
        acc[nb][3] = __expf(acc[nb][3] - mx2);
        s1 += acc[nb][0] + acc[nb][1];
        s2 += acc[nb][2] + acc[nb][3];
    }
    s1 += __shfl_xor_sync(0xffffffffu, s1, 1);
    s1 += __shfl_xor_sync(0xffffffffu, s1, 2);
    s2 += __shfl_xor_sync(0xffffffffu, s2, 1);
    s2 += __shfl_xor_sync(0xffffffffu, s2, 2);
    if (t4 == 0) {
        rinv[warp * 16 + g] = 1.f / s1;
        rinv[warp * 16 + 8 + g] = 1.f / s2;
    }
    // store P (tf32-rounded, unnormalized) back to sp
#pragma unroll
    for (int nb = 0; nb < 7; nb++) {
        *(float2*)&sp[base + nb * 8 + 2 * t4]  = make_float2(f2tf_f(acc[nb][0]), f2tf_f(acc[nb][1]));
        *(float2*)&sp[base2 + nb * 8 + 2 * t4] = make_float2(f2tf_f(acc[nb][2]), f2tf_f(acc[nb][3]));
    }
    __syncwarp();

    // phase 4: PV (each warp reads only its own 16 P-rows)
    float acc2[4][4];
#pragma unroll
    for (int i = 0; i < 4; i++)
#pragma unroll
        for (int j = 0; j < 4; j++) acc2[i][j] = 0.f;
#pragma unroll
    for (int kb2 = 0; kb2 < 7; kb2++) {
        float4 a;
        a.x = sp[base + kb2 * 8 + t4];
        a.y = sp[base2 + kb2 * 8 + t4];
        a.z = sp[base + kb2 * 8 + t4 + 4];
        a.w = sp[base2 + kb2 * 8 + t4 + 4];
#pragma unroll
        for (int nb = 0; nb < 4; nb++) {
            float2 bv = *(const float2*)&vs[(((kb2 << 2) + nb) * 32 + lane) * 2];
            mma_tf32(acc2[nb], a, bv.x, bv.y);
        }
    }

    // epilogue: normalize + write A'-permuted AO
    int i1 = warp * 16 + g, i2 = i1 + 8;
    float ri1 = rinv[i1], ri2 = rinv[i2];
    long m1 = (long)b * NT + i1, m2 = (long)b * NT + i2;
#pragma unroll
    for (int nb = 0; nb < 4; nb++) {
        int d0 = nb * 8 + 2 * t4;
        if (i1 < NT) {
            long off = a_perm_off(m1, h * HD + d0);
            AO[off]     = f2tf_f(acc2[nb][0] * ri1);
            AO[off + 4] = f2tf_f(acc2[nb][1] * ri1);
        }
        if (i2 < NT) {
            long off = a_perm_off(m2, h * HD + d0);
            AO[off]     = f2tf_f(acc2[nb][2] * ri2);
            AO[off + 4] = f2tf_f(acc2[nb][3] * ri2);
        }
    }
}

// ---------------- launch ----------------
extern "C" void kernel_launch(void* const* d_in, const int* in_sizes, int n_in,
                              void* d_out, int out_size) {
    const float* x          = (const float*)d_in[0];
    const float* mask       = (const float*)d_in[1];
    const float* qkv_w      = (const float*)d_in[2];
    const float* qkv_b      = (const float*)d_in[3];
    const float* qkv_down   = (const float*)d_in[4];
    const float* qkv_up     = (const float*)d_in[5];
    const float* qkv_gate   = (const float*)d_in[6];
    const float* qkv_res    = (const float*)d_in[7];
    const float* proj_w     = (const float*)d_in[8];
    const float* proj_b     = (const float*)d_in[9];
    const float* proj_down  = (const float*)d_in[10];
    const float* proj_up    = (const float*)d_in[11];
    const float* proj_gate  = (const float*)d_in[12];
    const float* proj_res   = (const float*)d_in[13];
    const float* bias_table = (const float*)d_in[14];
    const int*   rel_index  = (const int*)d_in[15];
    float* out = (float*)d_out;

    float *pT, *pX, *pAO, *pWq, *pWp;
    cudaGetSymbolAddress((void**)&pT, g_T);
    cudaGetSymbolAddress((void**)&pX, g_X);
    cudaGetSymbolAddress((void**)&pAO, g_AO);
    cudaGetSymbolAddress((void**)&pWq, g_Wqkv);
    cudaGetSymbolAddress((void**)&pWp, g_Wproj);

    int smem = 2 * ST_FL * sizeof(float);   // 49152 bytes
    cudaFuncSetAttribute(gemm_mma_kernel<0>, cudaFuncAttributeMaxDynamicSharedMemorySize, smem);
    cudaFuncSetAttribute(gemm_mma_kernel<1>, cudaFuncAttributeMaxDynamicSharedMemorySize, smem);

    prep_kernel<<<1024, 256>>>(qkv_w, qkv_res, qkv_gate, proj_w, proj_res, proj_gate,
                               bias_table, rel_index);
    lora_down_kernel<0><<<M_TOK / 16, 256>>>(x, qkv_down, pT, pX);
    dim3 gq(M_TOK / BM, QKV_NPACK / BNP);   // (1568, 18)
    gemm_mma_kernel<0><<<gq, 256, smem>>>(pX, pWq, qkv_b, qkv_up, pT, nullptr);
    attn_kernel<<<2048 * NH, 128>>>(mask, pAO);
    lora_down_kernel<1><<<M_TOK / 16, 256>>>(pAO, proj_down, pT, nullptr);
    dim3 gp(M_TOK / BM, PROJ_NPACK / BNP);  // (1568, 6)
    gemm_mma_kernel<1><<<gp, 256, smem>>>(pAO, pWp, proj_b, proj_up, pT, out);
}

// round 9
// speedup vs baseline: 2.6232x; 1.0905x over previous
#include <cuda_runtime.h>
#include <cstdint>
#include <math.h>

// ---------------- problem constants ----------------
#define M_TOK 100352            // 2048 * 49 tokens
#define DIM   384
#define NH    12
#define HD    32
#define NT    49
#define NWIN  64
#define RANK  16
#define QKV_NPACK 2304          // interleaved (main,gate) rows
#define PROJ_NPACK 768
#define SCALE_Q 0.17677669529663687f
#define NKB   (DIM / 8)         // 48 k-blocks of 8

// Fragment-permuted global layouts:
//  A'[m>>4][k>>3][lane][4] : lane=(m&7)*4+(k&3), inner=(m>>3&1)+2*((k>>2)&1)
//  B'[n>>3][k>>3][lane][2] : lane=(n&7)*4+(k&3), inner=(k>>2)&1
#define A_MB_STRIDE (NKB * 128)   // 6144 floats per 16-row block
#define B_NB_STRIDE (NKB * 64)    // 3072 floats per 8-row block

// Per-(b,h) attention fragment blocks (padding rows stay zero: never written)
#define QF_STRIDE 2048            // [4 mb][4 kb][32 lane][4]
#define KF_STRIDE 1792            // [7 nb][4 kb][32 lane][2]
#define VF_STRIDE 1792            // [7 kb2][4 nb][32 lane][2]

// ---------------- scratch: device globals ----------------
__device__ float g_Wqkv[QKV_NPACK * DIM];   // B'-permuted packed weights
__device__ float g_Wproj[PROJ_NPACK * DIM];
__device__ float g_bias[NH * NT * NT];
__device__ float g_T[M_TOK * RANK];
__device__ float g_X[M_TOK * DIM];          // A'-permuted tf32-rounded x
__device__ float g_Qf[24576L * QF_STRIDE];  // Q in attn A-frag layout (pre-scaled)
__device__ float g_Kf[24576L * KF_STRIDE];  // K in attn B-frag layout
__device__ float g_Vf[24576L * VF_STRIDE];  // V in attn PV B-frag layout
__device__ float g_AO[M_TOK * DIM];         // A'-permuted tf32-rounded attn output

// ---------------- helpers ----------------
__device__ __forceinline__ float f2tf_f(float f) {
    uint32_t u;
    asm("cvt.rna.tf32.f32 %0, %1;" : "=r"(u) : "f"(f));
    return __uint_as_float(u);
}
__device__ __forceinline__ void mma_tf32(float* c, const float4& a, float b0, float b1) {
    asm volatile(
        "mma.sync.aligned.m16n8k8.row.col.f32.tf32.tf32.f32 "
        "{%0,%1,%2,%3},{%4,%5,%6,%7},{%8,%9},{%0,%1,%2,%3};"
        : "+f"(c[0]), "+f"(c[1]), "+f"(c[2]), "+f"(c[3])
        : "r"(__float_as_uint(a.x)), "r"(__float_as_uint(a.y)),
          "r"(__float_as_uint(a.z)), "r"(__float_as_uint(a.w)),
          "r"(__float_as_uint(b0)), "r"(__float_as_uint(b1)));
}
__device__ __forceinline__ void cp16(void* s, const void* g) {
    uint32_t sa = (uint32_t)__cvta_generic_to_shared(s);
    asm volatile("cp.async.cg.shared.global [%0], [%1], 16;" :: "r"(sa), "l"(g));
}
__device__ __forceinline__ void cp_commit() { asm volatile("cp.async.commit_group;"); }
template <int N>
__device__ __forceinline__ void cp_wait() { asm volatile("cp.async.wait_group %0;" :: "n"(N)); }

__device__ __forceinline__ long a_perm_off(long m, int k) {
    return ((m >> 4) * NKB + (k >> 3)) * 128
         + (((int)(m & 7)) * 4 + (k & 3)) * 4
         + ((int)((m >> 3) & 1)) + (((k >> 2) & 1) << 1);
}

// ---------------- prep ----------------
__global__ void prep_kernel(const float* __restrict__ qkv_w, const float* __restrict__ qkv_res,
                            const float* __restrict__ qkv_gate,
                            const float* __restrict__ proj_w, const float* __restrict__ proj_res,
                            const float* __restrict__ proj_gate,
                            const float* __restrict__ bias_table, const int* __restrict__ rel_index) {
    int stride = gridDim.x * blockDim.x;
    int tid = blockIdx.x * blockDim.x + threadIdx.x;
    auto boff = [](int np, int k) {
        return (long)((np >> 3) * NKB + (k >> 3)) * 64 + ((np & 7) * 4 + (k & 3)) * 2 + ((k >> 2) & 1);
    };
    for (int e = tid; e < (QKV_NPACK / 2) * DIM; e += stride) {
        int n = e / DIM, k = e % DIM;
        g_Wqkv[boff(2 * n, k)]     = f2tf_f(qkv_w[e] + qkv_res[e]);
        g_Wqkv[boff(2 * n + 1, k)] = f2tf_f(qkv_gate[e]);
    }
    for (int e = tid; e < (PROJ_NPACK / 2) * DIM; e += stride) {
        int n = e / DIM, k = e % DIM;
        g_Wproj[boff(2 * n, k)]     = f2tf_f(proj_w[e] + proj_res[e]);
        g_Wproj[boff(2 * n + 1, k)] = f2tf_f(proj_gate[e]);
    }
    for (int e = tid; e < NH * NT * NT; e += stride) {
        int h = e / (NT * NT);
        int ij = e % (NT * NT);
        g_bias[e] = bias_table[rel_index[ij] * NH + h];
    }
}

// ---------------- lora down: T = X @ down^T (fp32); optional permuted tf32 copy ----------------
// PERM=0: X is row-linear. PERM=1: X is A'-fragment-permuted.
#define DSTR 385
template <int PERM>
__global__ void __launch_bounds__(256) lora_down_kernel(const float* __restrict__ X,
                                                        const float* __restrict__ down,
                                                        float* __restrict__ T,
                                                        float* __restrict__ Xr) {
    __shared__ float xs[16][DIM];
    __shared__ float ds[RANK * DSTR];
    long m0 = (long)blockIdx.x * 16;
    if (PERM == 0) {
        for (int e = threadIdx.x; e < 16 * DIM; e += 256)
            xs[e / DIM][e % DIM] = X[m0 * DIM + e];
    } else {
        const float* Xb = X + (m0 >> 4) * A_MB_STRIDE;
        for (int e = threadIdx.x; e < 16 * DIM; e += 256) {
            int kb = e >> 7;
            int rem = e & 127;
            int lane = rem >> 2, inner = rem & 3;
            int ml = (lane >> 2) + ((inner & 1) << 3);
            int k = kb * 8 + (lane & 3) + ((inner >> 1) << 2);
            xs[ml][k] = Xb[e];
        }
    }
    for (int e = threadIdx.x; e < RANK * DIM; e += 256)
        ds[(e / DIM) * DSTR + (e % DIM)] = down[e];
    __syncthreads();
    if (Xr) {
        for (int e = threadIdx.x; e < 16 * DIM; e += 256) {
            int ml = e / DIM, k = e % DIM;
            Xr[a_perm_off(m0 + ml, k)] = f2tf_f(xs[ml][k]);
        }
    }
    int ml = threadIdx.x / RANK;
    int r = threadIdx.x % RANK;
    const float* dr = ds + r * DSTR;
    float acc = 0.f;
#pragma unroll 8
    for (int k = 0; k < DIM; k++) acc += xs[ml][k] * dr[k];
    T[(m0 + ml) * RANK + r] = acc;
}

// ---------------- tf32 mma.sync GEMM, fragment-permuted operands, 3-stage pipeline ----------------
#define BM 64
#define BNP 128                 // packed columns (64 real outputs)
#define BK 32
#define NCH (DIM / BK)          // 12
#define A_ST (BM * BK)          // 2048 floats / stage
#define B_ST (BNP * BK)         // 4096 floats / stage
#define ST_FL (A_ST + B_ST)     // 6144 floats / stage
#define NSTG 3

template <int MODE>  // 0 = qkv scatter to frag layouts, 1 = proj write
__global__ void __launch_bounds__(256, 3) gemm_mma_kernel(
    const float* __restrict__ A, const float* __restrict__ Bp,
    const float* __restrict__ bias, const float* __restrict__ U,
    const float* __restrict__ T, float* __restrict__ outp) {
    extern __shared__ float sm[];

    int tid = threadIdx.x;
    int warp = tid >> 5, lane = tid & 31;
    int g = lane >> 2, t4 = lane & 3;
    int wm = (warp >> 2) * 32;        // 2 M-stripes of 32
    int wn = (warp & 3) * 32;         // 4 N-stripes of 32 packed
    int mb_w = (warp >> 2) * 2;       // A 16-row blocks within tile
    int nb_w = (warp & 3) * 4;        // B 8-row blocks within tile
    long m0 = (long)blockIdx.x * BM;
    long mb0 = m0 >> 4;
    int n0p = blockIdx.y * BNP;
    int nb0 = n0p >> 3;
    int n0r = n0p >> 1;

    float acc[2][4][4];
#pragma unroll
    for (int i = 0; i < 2; i++)
#pragma unroll
        for (int j = 0; j < 4; j++)
#pragma unroll
            for (int c = 0; c < 4; c++) acc[i][j][c] = 0.f;

    auto load_chunk = [&](int c, int s) {
        float* As = sm + s * ST_FL;
        float* Bs = As + A_ST;
        const float* Agc = A + mb0 * A_MB_STRIDE + c * 512;   // 4 kb * 128 floats
        const float* Bgc = Bp + (long)nb0 * B_NB_STRIDE + c * 256;
#pragma unroll
        for (int q = 0; q < 2; q++) {          // A: 512 16B chunks (4 runs of 2KB)
            int cid = tid + q * 256;
            int mb = cid >> 7, r = cid & 127;
            cp16(&As[mb * 512 + r * 4], Agc + (long)mb * A_MB_STRIDE + r * 4);
        }
#pragma unroll
        for (int q = 0; q < 4; q++) {          // B: 1024 16B chunks (16 runs of 1KB)
            int cid = tid + q * 256;
            int nb = cid >> 6, r = cid & 63;
            cp16(&Bs[nb * 256 + r * 4], Bgc + (long)nb * B_NB_STRIDE + r * 4);
        }
    };

    load_chunk(0, 0); cp_commit();
    load_chunk(1, 1); cp_commit();
    for (int c = 0; c < NCH; c++) {
        if (c < NCH - 1) cp_wait<1>();
        else cp_wait<0>();
        __syncthreads();
        if (c + 2 < NCH) {                 // buffer (c+2)%3 last read at compute(c-1): safe
            load_chunk(c + 2, (c + 2) % NSTG);
            cp_commit();
        }
        const float* Ab = sm + (c % NSTG) * ST_FL;
        const float* Bb = Ab + A_ST;
#pragma unroll
        for (int ks = 0; ks < 4; ks++) {
            float4 af[2];
            float2 bf[4];
#pragma unroll
            for (int mi = 0; mi < 2; mi++)
                af[mi] = *(const float4*)&Ab[(((mb_w + mi) << 2) + ks) * 128 + lane * 4];
#pragma unroll
            for (int ni = 0; ni < 4; ni++)
                bf[ni] = *(const float2*)&Bb[(((nb_w + ni) << 2) + ks) * 64 + lane * 2];
#pragma unroll
            for (int mi = 0; mi < 2; mi++)
#pragma unroll
                for (int ni = 0; ni < 4; ni++)
                    mma_tf32(acc[mi][ni], af[mi], bf[ni].x, bf[ni].y);
        }
    }

    // -------- epilogue: stage T/U, lora + bias + sigmoid gate, scatter --------
    // Ts/Us live in stage-0 region: last read of stage 0 was compute(9); all warps are
    // past it (program order through the iter-10/11 barriers).
    float* Ts = sm;              // [64][17]
    float* Us = sm + BM * 17;    // [64][17]
    for (int e = tid; e < BM * RANK; e += 256) {
        int i = e >> 4, r = e & 15;
        Ts[i * 17 + r] = T[(m0 + i) * RANK + r];
    }
    for (int e = tid; e < 64 * RANK; e += 256) {
        int i = e >> 4, r = e & 15;
        Us[i * 17 + r] = U[(n0r + i) * RANK + r];
    }
    __syncthreads();

    float lor[4][4];
#pragma unroll
    for (int i = 0; i < 4; i++)
#pragma unroll
        for (int j = 0; j < 4; j++) lor[i][j] = 0.f;
#pragma unroll
    for (int r = 0; r < RANK; r++) {
        float tv[4], uv[4];
#pragma unroll
        for (int mi = 0; mi < 2; mi++)
#pragma unroll
            for (int rr = 0; rr < 2; rr++)
                tv[mi * 2 + rr] = Ts[(wm + mi * 16 + g + rr * 8) * 17 + r];
#pragma unroll
        for (int ni = 0; ni < 4; ni++)
            uv[ni] = Us[((wn >> 1) + ni * 4 + t4) * 17 + r];
#pragma unroll
        for (int i = 0; i < 4; i++)
#pragma unroll
            for (int j = 0; j < 4; j++) lor[i][j] += tv[i] * uv[j];
    }

    float bv[4];
#pragma unroll
    for (int ni = 0; ni < 4; ni++) bv[ni] = __ldg(&bias[n0r + (wn >> 1) + ni * 4 + t4]);

#pragma unroll
    for (int mi = 0; mi < 2; mi++) {
#pragma unroll
        for (int rr = 0; rr < 2; rr++) {
            long m = m0 + wm + mi * 16 + g + rr * 8;
            long bb = m / NT;
            int t = (int)(m % NT);
#pragma unroll
            for (int ni = 0; ni < 4; ni++) {
                int n = n0r + (wn >> 1) + ni * 4 + t4;
                float mainv = acc[mi][ni][rr * 2 + 0];
                float gatev = acc[mi][ni][rr * 2 + 1];
                float gsig = 1.f / (1.f + __expf(-gatev));
                float val = mainv + bv[ni] + gsig * 2.0f * lor[mi * 2 + rr][ni];
                if (MODE == 0) {
                    int s = n / 384;
                    int rem = n - s * 384;
                    int hh = rem >> 5, d = rem & 31;
                    long bh2 = bb * NH + hh;
                    if (s == 0) {
                        long off = bh2 * QF_STRIDE + (((t >> 4) << 2) + (d >> 3)) * 128
                                 + (((t & 7) << 2) + (d & 3)) * 4 + ((t >> 3) & 1) + (((d >> 2) & 1) << 1);
                        g_Qf[off] = f2tf_f(val * SCALE_Q);
                    } else if (s == 1) {
                        long off = bh2 * KF_STRIDE + (((t >> 3) << 2) + (d >> 3)) * 64
                                 + (((t & 7) << 2) + (d & 3)) * 2 + ((d >> 2) & 1);
                        g_Kf[off] = f2tf_f(val);
                    } else {
                        long off = bh2 * VF_STRIDE + (((t >> 3) << 2) + (d >> 3)) * 64
                                 + (((d & 7) << 2) + (t & 3)) * 2 + ((t >> 2) & 1);
                        g_Vf[off] = f2tf_f(val);
                    }
                } else {
                    outp[m * DIM + n] = val;
                }
            }
        }
    }
}

// ---------------- windowed attention, tensor-core, pre-fragmented operands ----------------
#define SPS 58
__global__ void __launch_bounds__(128, 6) attn_kernel(const float* __restrict__ mask,
                                                      float* __restrict__ AO) {
    __shared__ __align__(16) float qs[QF_STRIDE];
    __shared__ __align__(16) float ks[KF_STRIDE];
    __shared__ __align__(16) float vs[VF_STRIDE];
    __shared__ float sp[64 * SPS];
    __shared__ float rinv[64];
    int bh = blockIdx.x;
    int b = bh / NH, h = bh % NH;
    int wdw = b % NWIN;
    int tid = threadIdx.x;
    int warp = tid >> 5, lane = tid & 31, g = lane >> 2, t4 = lane & 3;

    // contiguous cp.async of pre-fragmented Q/K/V (padding rows are static zeros)
    const float* Qf = g_Qf + (long)bh * QF_STRIDE;
    const float* Kf = g_Kf + (long)bh * KF_STRIDE;
    const float* Vf = g_Vf + (long)bh * VF_STRIDE;
    for (int c = tid; c < QF_STRIDE / 4; c += 128) cp16(&qs[c * 4], Qf + (long)c * 4);
    for (int c = tid; c < KF_STRIDE / 4; c += 128) cp16(&ks[c * 4], Kf + (long)c * 4);
    for (int c = tid; c < VF_STRIDE / 4; c += 128) cp16(&vs[c * 4], Vf + (long)c * 4);
    cp_commit();

    // score board: bias + mask for (i,j) < 49, -1e30 padding elsewhere
    const float* bi = g_bias + h * NT * NT;
    const float* mk = mask + (long)wdw * NT * NT;
    for (int e = tid; e < 64 * SPS; e += 128) {
        int i = e / SPS, j = e - i * SPS;
        sp[e] = (i < NT && j < NT) ? bi[i * NT + j] + mk[i * NT + j] : -1e30f;
    }
    cp_wait<0>();
    __syncthreads();

    // QK^T with bias+mask as accumulator init
    int base = (warp * 16 + g) * SPS;
    int base2 = base + 8 * SPS;
    float acc[7][4];
#pragma unroll
    for (int nb = 0; nb < 7; nb++) {
        float2 x = *(const float2*)&sp[base + nb * 8 + 2 * t4];
        float2 y = *(const float2*)&sp[base2 + nb * 8 + 2 * t4];
        acc[nb][0] = x.x; acc[nb][1] = x.y; acc[nb][2] = y.x; acc[nb][3] = y.y;
    }
#pragma unroll
    for (int kb = 0; kb < 4; kb++) {
        float4 a = *(const float4*)&qs[(((warp << 2) + kb) * 32 + lane) * 4];
#pragma unroll
        for (int nb = 0; nb < 7; nb++) {
            float2 bv = *(const float2*)&ks[(((nb << 2) + kb) * 32 + lane) * 2];
            mma_tf32(acc[nb], a, bv.x, bv.y);
        }
    }

    // softmax in fragments: rows (warp*16+g) and (+8), spread over 4 t4-lanes
    float mx1 = -1e30f, mx2 = -1e30f;
#pragma unroll
    for (int nb = 0; nb < 7; nb++) {
        mx1 = fmaxf(mx1, fmaxf(acc[nb][0], acc[nb][1]));
        mx2 = fmaxf(mx2, fmaxf(acc[nb][2], acc[nb][3]));
    }
    mx1 = fmaxf(mx1, __shfl_xor_sync(0xffffffffu, mx1, 1));
    mx1 = fmaxf(mx1, __shfl_xor_sync(0xffffffffu, mx1, 2));
    mx2 = fmaxf(mx2, __shfl_xor_sync(0xffffffffu, mx2, 1));
    mx2 = fmaxf(mx2, __shfl_xor_sync(0xffffffffu, mx2, 2));
    float s1 = 0.f, s2 = 0.f;
#pragma unroll
    for (int nb = 0; nb < 7; nb++) {
        acc[nb][0] = __expf(acc[nb][0] - mx1);
        acc[nb][1] = __expf(acc[nb][1] - mx1);
        acc[nb][2] = __expf(acc[nb][2] - mx2);
        acc[nb][3] = __expf(acc[nb][3] - mx2);
        s1 += acc[nb][0] + acc[nb][1];
        s2 += acc[nb][2] + acc[nb][3];
    }
    s1 += __shfl_xor_sync(0xffffffffu, s1, 1);
    s1 += __shfl_xor_sync(0xffffffffu, s1, 2);
    s2 += __shfl_xor_sync(0xffffffffu, s2, 1);
    s2 += __shfl_xor_sync(0xffffffffu, s2, 2);
    if (t4 == 0) {
        rinv[warp * 16 + g] = 1.f / s1;
        rinv[warp * 16 + 8 + g] = 1.f / s2;
    }
#pragma unroll
    for (int nb = 0; nb < 7; nb++) {
        *(float2*)&sp[base + nb * 8 + 2 * t4]  = make_float2(f2tf_f(acc[nb][0]), f2tf_f(acc[nb][1]));
        *(float2*)&sp[base2 + nb * 8 + 2 * t4] = make_float2(f2tf_f(acc[nb][2]), f2tf_f(acc[nb][3]));
    }
    __syncwarp();

    // PV (each warp reads only its own 16 P-rows)
    float acc2[4][4];
#pragma unroll
    for (int i = 0; i < 4; i++)
#pragma unroll
        for (int j = 0; j < 4; j++) acc2[i][j] = 0.f;
#pragma unroll
    for (int kb2 = 0; kb2 < 7; kb2++) {
        float4 a;
        a.x = sp[base + kb2 * 8 + t4];
        a.y = sp[base2 + kb2 * 8 + t4];
        a.z = sp[base + kb2 * 8 + t4 + 4];
        a.w = sp[base2 + kb2 * 8 + t4 + 4];
#pragma unroll
        for (int nb = 0; nb < 4; nb++) {
            float2 bv = *(const float2*)&vs[(((kb2 << 2) + nb) * 32 + lane) * 2];
            mma_tf32(acc2[nb], a, bv.x, bv.y);
        }
    }

    // epilogue: normalize + write A'-permuted AO
    int i1 = warp * 16 + g, i2 = i1 + 8;
    float ri1 = rinv[i1], ri2 = rinv[i2];
    long m1 = (long)b * NT + i1, m2 = (long)b * NT + i2;
#pragma unroll
    for (int nb = 0; nb < 4; nb++) {
        int d0 = nb * 8 + 2 * t4;
        if (i1 < NT) {
            long off = a_perm_off(m1, h * HD + d0);
            AO[off]     = f2tf_f(acc2[nb][0] * ri1);
            AO[off + 4] = f2tf_f(acc2[nb][1] * ri1);
        }
        if (i2 < NT) {
            long off = a_perm_off(m2, h * HD + d0);
            AO[off]     = f2tf_f(acc2[nb][2] * ri2);
            AO[off + 4] = f2tf_f(acc2[nb][3] * ri2);
        }
    }
}

// ---------------- launch ----------------
extern "C" void kernel_launch(void* const* d_in, const int* in_sizes, int n_in,
                              void* d_out, int out_size) {
    const float* x          = (const float*)d_in[0];
    const float* mask       = (const float*)d_in[1];
    const float* qkv_w      = (const float*)d_in[2];
    const float* qkv_b      = (const float*)d_in[3];
    const float* qkv_down   = (const float*)d_in[4];
    const float* qkv_up     = (const float*)d_in[5];
    const float* qkv_gate   = (const float*)d_in[6];
    const float* qkv_res    = (const float*)d_in[7];
    const float* proj_w     = (const float*)d_in[8];
    const float* proj_b     = (const float*)d_in[9];
    const float* proj_down  = (const float*)d_in[10];
    const float* proj_up    = (const float*)d_in[11];
    const float* proj_gate  = (const float*)d_in[12];
    const float* proj_res   = (const float*)d_in[13];
    const float* bias_table = (const float*)d_in[14];
    const int*   rel_index  = (const int*)d_in[15];
    float* out = (float*)d_out;

    float *pT, *pX, *pAO, *pWq, *pWp;
    cudaGetSymbolAddress((void**)&pT, g_T);
    cudaGetSymbolAddress((void**)&pX, g_X);
    cudaGetSymbolAddress((void**)&pAO, g_AO);
    cudaGetSymbolAddress((void**)&pWq, g_Wqkv);
    cudaGetSymbolAddress((void**)&pWp, g_Wproj);

    int smem = NSTG * ST_FL * sizeof(float);   // 73728 bytes
    cudaFuncSetAttribute(gemm_mma_kernel<0>, cudaFuncAttributeMaxDynamicSharedMemorySize, smem);
    cudaFuncSetAttribute(gemm_mma_kernel<1>, cudaFuncAttributeMaxDynamicSharedMemorySize, smem);

    prep_kernel<<<1024, 256>>>(qkv_w, qkv_res, qkv_gate, proj_w, proj_res, proj_gate,
                               bias_table, rel_index);
    lora_down_kernel<0><<<M_TOK / 16, 256>>>(x, qkv_down, pT, pX);
    dim3 gq(M_TOK / BM, QKV_NPACK / BNP);   // (1568, 18)
    gemm_mma_kernel<0><<<gq, 256, smem>>>(pX, pWq, qkv_b, qkv_up, pT, nullptr);
    attn_kernel<<<2048 * NH, 128>>>(mask, pAO);
    lora_down_kernel<1><<<M_TOK / 16, 256>>>(pAO, proj_down, pT, nullptr);
    dim3 gp(M_TOK / BM, PROJ_NPACK / BNP);  // (1568, 6)
    gemm_mma_kernel<1><<<gp, 256, smem>>>(pAO, pWp, proj_b, proj_up, pT, out);
}

// round 10
// speedup vs baseline: 2.8379x; 1.0818x over previous
#include <cuda_runtime.h>
#include <cstdint>
#include <math.h>

// ---------------- problem constants ----------------
#define M_TOK 100352            // 2048 * 49 tokens
#define DIM   384
#define NH    12
#define HD    32
#define NT    49
#define NWIN  64
#define RANK  16
#define QKV_NPACK 2304          // interleaved (main,gate) rows
#define PROJ_NPACK 768
#define SCALE_Q 0.17677669529663687f
#define NKB   (DIM / 8)         // 48 k-blocks of 8

// Fragment-permuted global layouts:
//  A'[m>>4][k>>3][lane][4] : lane=(m&7)*4+(k&3), inner=(m>>3&1)+2*((k>>2)&1)
//  B'[n>>3][k>>3][lane][2] : lane=(n&7)*4+(k&3), inner=(k>>2)&1
#define A_MB_STRIDE (NKB * 128)   // 6144 floats per 16-row block
#define B_NB_STRIDE (NKB * 64)    // 3072 floats per 8-row block

// Per-(b,h) attention fragment blocks (padding rows stay zero: never written)
#define QF_STRIDE 2048            // [4 mb][4 kb][32 lane][4]
#define KF_STRIDE 1792            // [7 nb][4 kb][32 lane][2]
#define VF_STRIDE 1792            // [7 kb2][4 nb][32 lane][2]

// ---------------- scratch: device globals ----------------
__device__ float g_Wqkv[QKV_NPACK * DIM];   // B'-permuted packed weights
__device__ float g_Wproj[PROJ_NPACK * DIM];
__device__ float g_bias[NH * NT * NT];
__device__ float g_T[M_TOK * RANK];
__device__ float g_X[M_TOK * DIM];          // A'-permuted tf32-rounded x
__device__ float g_Qf[24576L * QF_STRIDE];  // Q in attn A-frag layout (pre-scaled)
__device__ float g_Kf[24576L * KF_STRIDE];  // K in attn B-frag layout
__device__ float g_Vf[24576L * VF_STRIDE];  // V in attn PV B-frag layout
__device__ float g_AO[M_TOK * DIM];         // A'-permuted tf32-rounded attn output

// ---------------- helpers ----------------
__device__ __forceinline__ float f2tf_f(float f) {
    uint32_t u;
    asm("cvt.rna.tf32.f32 %0, %1;" : "=r"(u) : "f"(f));
    return __uint_as_float(u);
}
__device__ __forceinline__ void mma_tf32(float* c, const float4& a, float b0, float b1) {
    asm volatile(
        "mma.sync.aligned.m16n8k8.row.col.f32.tf32.tf32.f32 "
        "{%0,%1,%2,%3},{%4,%5,%6,%7},{%8,%9},{%0,%1,%2,%3};"
        : "+f"(c[0]), "+f"(c[1]), "+f"(c[2]), "+f"(c[3])
        : "r"(__float_as_uint(a.x)), "r"(__float_as_uint(a.y)),
          "r"(__float_as_uint(a.z)), "r"(__float_as_uint(a.w)),
          "r"(__float_as_uint(b0)), "r"(__float_as_uint(b1)));
}
__device__ __forceinline__ void cp16(void* s, const void* g) {
    uint32_t sa = (uint32_t)__cvta_generic_to_shared(s);
    asm volatile("cp.async.cg.shared.global [%0], [%1], 16;" :: "r"(sa), "l"(g));
}
__device__ __forceinline__ void cp_commit() { asm volatile("cp.async.commit_group;"); }
template <int N>
__device__ __forceinline__ void cp_wait() { asm volatile("cp.async.wait_group %0;" :: "n"(N)); }

__device__ __forceinline__ long a_perm_off(long m, int k) {
    return ((m >> 4) * NKB + (k >> 3)) * 128
         + (((int)(m & 7)) * 4 + (k & 3)) * 4
         + ((int)((m >> 3) & 1)) + (((k >> 2) & 1) << 1);
}

// ---------------- prep ----------------
__global__ void prep_kernel(const float* __restrict__ qkv_w, const float* __restrict__ qkv_res,
                            const float* __restrict__ qkv_gate,
                            const float* __restrict__ proj_w, const float* __restrict__ proj_res,
                            const float* __restrict__ proj_gate,
                            const float* __restrict__ bias_table, const int* __restrict__ rel_index) {
    int stride = gridDim.x * blockDim.x;
    int tid = blockIdx.x * blockDim.x + threadIdx.x;
    auto boff = [](int np, int k) {
        return (long)((np >> 3) * NKB + (k >> 3)) * 64 + ((np & 7) * 4 + (k & 3)) * 2 + ((k >> 2) & 1);
    };
    for (int e = tid; e < (QKV_NPACK / 2) * DIM; e += stride) {
        int n = e / DIM, k = e % DIM;
        g_Wqkv[boff(2 * n, k)]     = f2tf_f(qkv_w[e] + qkv_res[e]);
        g_Wqkv[boff(2 * n + 1, k)] = f2tf_f(qkv_gate[e]);
    }
    for (int e = tid; e < (PROJ_NPACK / 2) * DIM; e += stride) {
        int n = e / DIM, k = e % DIM;
        g_Wproj[boff(2 * n, k)]     = f2tf_f(proj_w[e] + proj_res[e]);
        g_Wproj[boff(2 * n + 1, k)] = f2tf_f(proj_gate[e]);
    }
    for (int e = tid; e < NH * NT * NT; e += stride) {
        int h = e / (NT * NT);
        int ij = e % (NT * NT);
        g_bias[e] = bias_table[rel_index[ij] * NH + h];
    }
}

// ---------------- lora down: T = X @ down^T (fp32); optional permuted tf32 copy ----------------
// PERM=0: X is row-linear. PERM=1: X is A'-fragment-permuted.
#define DSTR 385
template <int PERM>
__global__ void __launch_bounds__(256) lora_down_kernel(const float* __restrict__ X,
                                                        const float* __restrict__ down,
                                                        float* __restrict__ T,
                                                        float* __restrict__ Xr) {
    __shared__ float xs[16][DIM];
    __shared__ float ds[RANK * DSTR];
    long m0 = (long)blockIdx.x * 16;
    if (PERM == 0) {
        for (int e = threadIdx.x; e < 16 * DIM; e += 256)
            xs[e / DIM][e % DIM] = X[m0 * DIM + e];
    } else {
        const float* Xb = X + (m0 >> 4) * A_MB_STRIDE;
        for (int e = threadIdx.x; e < 16 * DIM; e += 256) {
            int kb = e >> 7;
            int rem = e & 127;
            int lane = rem >> 2, inner = rem & 3;
            int ml = (lane >> 2) + ((inner & 1) << 3);
            int k = kb * 8 + (lane & 3) + ((inner >> 1) << 2);
            xs[ml][k] = Xb[e];
        }
    }
    for (int e = threadIdx.x; e < RANK * DIM; e += 256)
        ds[(e / DIM) * DSTR + (e % DIM)] = down[e];
    __syncthreads();
    if (Xr) {
        for (int e = threadIdx.x; e < 16 * DIM; e += 256) {
            int ml = e / DIM, k = e % DIM;
            Xr[a_perm_off(m0 + ml, k)] = f2tf_f(xs[ml][k]);
        }
    }
    int ml = threadIdx.x / RANK;
    int r = threadIdx.x % RANK;
    const float* dr = ds + r * DSTR;
    float acc = 0.f;
#pragma unroll 8
    for (int k = 0; k < DIM; k++) acc += xs[ml][k] * dr[k];
    T[(m0 + ml) * RANK + r] = acc;
}

// ---------------- tf32 mma.sync GEMM, fragment-permuted operands, 3-stage pipeline ----------------
// BM=128 x BNP=128, 8 warps as 2m x 4n, warp tile 64m x 32np (acc 64 regs).
#define BM 128
#define BNP 128                 // packed columns (64 real outputs)
#define BK 32
#define NCH (DIM / BK)          // 12
#define A_ST (BM * BK)          // 4096 floats / stage
#define B_ST (BNP * BK)         // 4096 floats / stage
#define ST_FL (A_ST + B_ST)     // 8192 floats / stage
#define NSTG 3

template <int MODE>  // 0 = qkv scatter to frag layouts, 1 = proj write
__global__ void __launch_bounds__(256, 2) gemm_mma_kernel(
    const float* __restrict__ A, const float* __restrict__ Bp,
    const float* __restrict__ bias, const float* __restrict__ U,
    const float* __restrict__ T, float* __restrict__ outp) {
    extern __shared__ float sm[];

    int tid = threadIdx.x;
    int warp = tid >> 5, lane = tid & 31;
    int g = lane >> 2, t4 = lane & 3;
    int warp_m = warp >> 2;           // 0..1, 64-row stripes
    int warp_n = warp & 3;            // 0..3, 32-packed stripes
    int wm = warp_m * 64;
    int wn = warp_n * 32;
    int mb_w = warp_m * 4;            // 4 A 16-row blocks per warp
    int nb_w = warp_n * 4;            // 4 B 8-row blocks per warp
    int n0p = blockIdx.x * BNP;       // n FASTEST in grid: A reused via L2
    long m0 = (long)blockIdx.y * BM;
    long mb0 = m0 >> 4;
    int nb0 = n0p >> 3;
    int n0r = n0p >> 1;

    float acc[4][4][4];
#pragma unroll
    for (int i = 0; i < 4; i++)
#pragma unroll
        for (int j = 0; j < 4; j++)
#pragma unroll
            for (int c = 0; c < 4; c++) acc[i][j][c] = 0.f;

    auto load_chunk = [&](int c, int s) {
        float* As = sm + s * ST_FL;
        float* Bs = As + A_ST;
        const float* Agc = A + mb0 * A_MB_STRIDE + c * 512;   // 4 kb * 128 floats per mb
        const float* Bgc = Bp + (long)nb0 * B_NB_STRIDE + c * 256;
#pragma unroll
        for (int q = 0; q < 4; q++) {          // A: 1024 16B chunks (8 mb-runs of 2KB)
            int cid = tid + q * 256;
            int mb = cid >> 7, r = cid & 127;
            cp16(&As[mb * 512 + r * 4], Agc + (long)mb * A_MB_STRIDE + r * 4);
        }
#pragma unroll
        for (int q = 0; q < 4; q++) {          // B: 1024 16B chunks (16 nb-runs of 1KB)
            int cid = tid + q * 256;
            int nb = cid >> 6, r = cid & 63;
            cp16(&Bs[nb * 256 + r * 4], Bgc + (long)nb * B_NB_STRIDE + r * 4);
        }
    };

    load_chunk(0, 0); cp_commit();
    load_chunk(1, 1); cp_commit();
    for (int c = 0; c < NCH; c++) {
        if (c < NCH - 1) cp_wait<1>();
        else cp_wait<0>();
        __syncthreads();
        if (c + 2 < NCH) {
            load_chunk(c + 2, (c + 2) % NSTG);
            cp_commit();
        }
        const float* Ab = sm + (c % NSTG) * ST_FL;
        const float* Bb = Ab + A_ST;
#pragma unroll
        for (int ks = 0; ks < 4; ks++) {
            float4 af[4];
            float2 bf[4];
#pragma unroll
            for (int mi = 0; mi < 4; mi++)
                af[mi] = *(const float4*)&Ab[(((mb_w + mi) << 2) + ks) * 128 + lane * 4];
#pragma unroll
            for (int ni = 0; ni < 4; ni++)
                bf[ni] = *(const float2*)&Bb[(((nb_w + ni) << 2) + ks) * 64 + lane * 2];
#pragma unroll
            for (int mi = 0; mi < 4; mi++)
#pragma unroll
                for (int ni = 0; ni < 4; ni++)
                    mma_tf32(acc[mi][ni], af[mi], bf[ni].x, bf[ni].y);
        }
    }

    // -------- epilogue: stage T/U, lora + bias + sigmoid gate, scatter --------
    float* Ts = sm;              // [128][17]
    float* Us = sm + BM * 17;    // [64][17]
    for (int e = tid; e < BM * RANK; e += 256) {
        int i = e >> 4, r = e & 15;
        Ts[i * 17 + r] = T[(m0 + i) * RANK + r];
    }
    for (int e = tid; e < 64 * RANK; e += 256) {
        int i = e >> 4, r = e & 15;
        Us[i * 17 + r] = U[(n0r + i) * RANK + r];
    }
    __syncthreads();

    float lor[8][4];
#pragma unroll
    for (int i = 0; i < 8; i++)
#pragma unroll
        for (int j = 0; j < 4; j++) lor[i][j] = 0.f;
#pragma unroll
    for (int r = 0; r < RANK; r++) {
        float tv[8], uv[4];
#pragma unroll
        for (int mi = 0; mi < 4; mi++)
#pragma unroll
            for (int rr = 0; rr < 2; rr++)
                tv[mi * 2 + rr] = Ts[(wm + mi * 16 + g + rr * 8) * 17 + r];
#pragma unroll
        for (int ni = 0; ni < 4; ni++)
            uv[ni] = Us[((wn >> 1) + ni * 4 + t4) * 17 + r];
#pragma unroll
        for (int i = 0; i < 8; i++)
#pragma unroll
            for (int j = 0; j < 4; j++) lor[i][j] += tv[i] * uv[j];
    }

    float bv[4];
#pragma unroll
    for (int ni = 0; ni < 4; ni++) bv[ni] = __ldg(&bias[n0r + (wn >> 1) + ni * 4 + t4]);

#pragma unroll
    for (int mi = 0; mi < 4; mi++) {
#pragma unroll
        for (int rr = 0; rr < 2; rr++) {
            long m = m0 + wm + mi * 16 + g + rr * 8;
            long bb = m / NT;
            int t = (int)(m % NT);
#pragma unroll
            for (int ni = 0; ni < 4; ni++) {
                int n = n0r + (wn >> 1) + ni * 4 + t4;
                float mainv = acc[mi][ni][rr * 2 + 0];
                float gatev = acc[mi][ni][rr * 2 + 1];
                float gsig = 1.f / (1.f + __expf(-gatev));
                float val = mainv + bv[ni] + gsig * 2.0f * lor[mi * 2 + rr][ni];
                if (MODE == 0) {
                    int s = n / 384;
                    int rem = n - s * 384;
                    int hh = rem >> 5, d = rem & 31;
                    long bh2 = bb * NH + hh;
                    if (s == 0) {
                        long off = bh2 * QF_STRIDE + (((t >> 4) << 2) + (d >> 3)) * 128
                                 + (((t & 7) << 2) + (d & 3)) * 4 + ((t >> 3) & 1) + (((d >> 2) & 1) << 1);
                        g_Qf[off] = f2tf_f(val * SCALE_Q);
                    } else if (s == 1) {
                        long off = bh2 * KF_STRIDE + (((t >> 3) << 2) + (d >> 3)) * 64
                                 + (((t & 7) << 2) + (d & 3)) * 2 + ((d >> 2) & 1);
                        g_Kf[off] = f2tf_f(val);
                    } else {
                        long off = bh2 * VF_STRIDE + (((t >> 3) << 2) + (d >> 3)) * 64
                                 + (((d & 7) << 2) + (t & 3)) * 2 + ((t >> 2) & 1);
                        g_Vf[off] = f2tf_f(val);
                    }
                } else {
                    outp[m * DIM + n] = val;
                }
            }
        }
    }
}

// ---------------- windowed attention, tensor-core, pre-fragmented operands ----------------
#define SPS 58
__global__ void __launch_bounds__(128, 6) attn_kernel(const float* __restrict__ mask,
                                                      float* __restrict__ AO) {
    __shared__ __align__(16) float qs[QF_STRIDE];
    __shared__ __align__(16) float ks[KF_STRIDE];
    __shared__ __align__(16) float vs[VF_STRIDE];
    __shared__ float sp[64 * SPS];
    __shared__ float rinv[64];
    int bh = blockIdx.x;
    int b = bh / NH, h = bh % NH;
    int wdw = b % NWIN;
    int tid = threadIdx.x;
    int warp = tid >> 5, lane = tid & 31, g = lane >> 2, t4 = lane & 3;

    const float* Qf = g_Qf + (long)bh * QF_STRIDE;
    const float* Kf = g_Kf + (long)bh * KF_STRIDE;
    const float* Vf = g_Vf + (long)bh * VF_STRIDE;
    for (int c = tid; c < QF_STRIDE / 4; c += 128) cp16(&qs[c * 4], Qf + (long)c * 4);
    for (int c = tid; c < KF_STRIDE / 4; c += 128) cp16(&ks[c * 4], Kf + (long)c * 4);
    for (int c = tid; c < VF_STRIDE / 4; c += 128) cp16(&vs[c * 4], Vf + (long)c * 4);
    cp_commit();

    const float* bi = g_bias + h * NT * NT;
    const float* mk = mask + (long)wdw * NT * NT;
    for (int e = tid; e < 64 * SPS; e += 128) {
        int i = e / SPS, j = e - i * SPS;
        sp[e] = (i < NT && j < NT) ? bi[i * NT + j] + mk[i * NT + j] : -1e30f;
    }
    cp_wait<0>();
    __syncthreads();

    int base = (warp * 16 + g) * SPS;
    int base2 = base + 8 * SPS;
    float acc[7][4];
#pragma unroll
    for (int nb = 0; nb < 7; nb++) {
        float2 x = *(const float2*)&sp[base + nb * 8 + 2 * t4];
        float2 y = *(const float2*)&sp[base2 + nb * 8 + 2 * t4];
        acc[nb][0] = x.x; acc[nb][1] = x.y; acc[nb][2] = y.x; acc[nb][3] = y.y;
    }
#pragma unroll
    for (int kb = 0; kb < 4; kb++) {
        float4 a = *(const float4*)&qs[(((warp << 2) + kb) * 32 + lane) * 4];
#pragma unroll
        for (int nb = 0; nb < 7; nb++) {
            float2 bv = *(const float2*)&ks[(((nb << 2) + kb) * 32 + lane) * 2];
            mma_tf32(acc[nb], a, bv.x, bv.y);
        }
    }

    float mx1 = -1e30f, mx2 = -1e30f;
#pragma unroll
    for (int nb = 0; nb < 7; nb++) {
        mx1 = fmaxf(mx1, fmaxf(acc[nb][0], acc[nb][1]));
        mx2 = fmaxf(mx2, fmaxf(acc[nb][2], acc[nb][3]));
    }
    mx1 = fmaxf(mx1, __shfl_xor_sync(0xffffffffu, mx1, 1));
    mx1 = fmaxf(mx1, __shfl_xor_sync(0xffffffffu, mx1, 2));
    mx2 = fmaxf(mx2, __shfl_xor_sync(0xffffffffu, mx2, 1));
    mx2 = fmaxf(mx2, __shfl_xor_sync(0xffffffffu, mx2, 2));
    float s1 = 0.f, s2 = 0.f;
#pragma unroll
    for (int nb = 0; nb < 7; nb++) {
        acc[nb][0] = __expf(acc[nb][0] - mx1);
        acc[nb][1] = __expf(acc[nb][1] - mx1);
        acc[nb][2] = __expf(acc[nb][2] - mx2);
        acc[nb][3] = __expf(acc[nb][3] - mx2);
        s1 += acc[nb][0] + acc[nb][1];
        s2 += acc[nb][2] + acc[nb][3];
    }
    s1 += __shfl_xor_sync(0xffffffffu, s1, 1);
    s1 += __shfl_xor_sync(0xffffffffu, s1, 2);
    s2 += __shfl_xor_sync(0xffffffffu, s2, 1);
    s2 += __shfl_xor_sync(0xffffffffu, s2, 2);
    if (t4 == 0) {
        rinv[warp * 16 + g] = 1.f / s1;
        rinv[warp * 16 + 8 + g] = 1.f / s2;
    }
#pragma unroll
    for (int nb = 0; nb < 7; nb++) {
        *(float2*)&sp[base + nb * 8 + 2 * t4]  = make_float2(f2tf_f(acc[nb][0]), f2tf_f(acc[nb][1]));
        *(float2*)&sp[base2 + nb * 8 + 2 * t4] = make_float2(f2tf_f(acc[nb][2]), f2tf_f(acc[nb][3]));
    }
    __syncwarp();

    float acc2[4][4];
#pragma unroll
    for (int i = 0; i < 4; i++)
#pragma unroll
        for (int j = 0; j < 4; j++) acc2[i][j] = 0.f;
#pragma unroll
    for (int kb2 = 0; kb2 < 7; kb2++) {
        float4 a;
        a.x = sp[base + kb2 * 8 + t4];
        a.y = sp[base2 + kb2 * 8 + t4];
        a.z = sp[base + kb2 * 8 + t4 + 4];
        a.w = sp[base2 + kb2 * 8 + t4 + 4];
#pragma unroll
        for (int nb = 0; nb < 4; nb++) {
            float2 bv = *(const float2*)&vs[(((kb2 << 2) + nb) * 32 + lane) * 2];
            mma_tf32(acc2[nb], a, bv.x, bv.y);
        }
    }

    int i1 = warp * 16 + g, i2 = i1 + 8;
    float ri1 = rinv[i1], ri2 = rinv[i2];
    long m1 = (long)b * NT + i1, m2 = (long)b * NT + i2;
#pragma unroll
    for (int nb = 0; nb < 4; nb++) {
        int d0 = nb * 8 + 2 * t4;
        if (i1 < NT) {
            long off = a_perm_off(m1, h * HD + d0);
            AO[off]     = f2tf_f(acc2[nb][0] * ri1);
            AO[off + 4] = f2tf_f(acc2[nb][1] * ri1);
        }
        if (i2 < NT) {
            long off = a_perm_off(m2, h * HD + d0);
            AO[off]     = f2tf_f(acc2[nb][2] * ri2);
            AO[off + 4] = f2tf_f(acc2[nb][3] * ri2);
        }
    }
}

// ---------------- launch ----------------
extern "C" void kernel_launch(void* const* d_in, const int* in_sizes, int n_in,
                              void* d_out, int out_size) {
    const float* x          = (const float*)d_in[0];
    const float* mask       = (const float*)d_in[1];
    const float* qkv_w      = (const float*)d_in[2];
    const float* qkv_b      = (const float*)d_in[3];
    const float* qkv_down   = (const float*)d_in[4];
    const float* qkv_up     = (const float*)d_in[5];
    const float* qkv_gate   = (const float*)d_in[6];
    const float* qkv_res    = (const float*)d_in[7];
    const float* proj_w     = (const float*)d_in[8];
    const float* proj_b     = (const float*)d_in[9];
    const float* proj_down  = (const float*)d_in[10];
    const float* proj_up    = (const float*)d_in[11];
    const float* proj_gate  = (const float*)d_in[12];
    const float* proj_res   = (const float*)d_in[13];
    const float* bias_table = (const float*)d_in[14];
    const int*   rel_index  = (const int*)d_in[15];
    float* out = (float*)d_out;

    float *pT, *pX, *pAO, *pWq, *pWp;
    cudaGetSymbolAddress((void**)&pT, g_T);
    cudaGetSymbolAddress((void**)&pX, g_X);
    cudaGetSymbolAddress((void**)&pAO, g_AO);
    cudaGetSymbolAddress((void**)&pWq, g_Wqkv);
    cudaGetSymbolAddress((void**)&pWp, g_Wproj);

    int smem = NSTG * ST_FL * sizeof(float);   // 98304 bytes
    cudaFuncSetAttribute(gemm_mma_kernel<0>, cudaFuncAttributeMaxDynamicSharedMemorySize, smem);
    cudaFuncSetAttribute(gemm_mma_kernel<1>, cudaFuncAttributeMaxDynamicSharedMemorySize, smem);

    prep_kernel<<<1024, 256>>>(qkv_w, qkv_res, qkv_gate, proj_w, proj_res, proj_gate,
                               bias_table, rel_index);
    lora_down_kernel<0><<<M_TOK / 16, 256>>>(x, qkv_down, pT, pX);
    dim3 gq(QKV_NPACK / BNP, M_TOK / BM);   // (18, 784): n fastest -> A read once
    gemm_mma_kernel<0><<<gq, 256, smem>>>(pX, pWq, qkv_b, qkv_up, pT, nullptr);
    attn_kernel<<<2048 * NH, 128>>>(mask, pAO);
    lora_down_kernel<1><<<M_TOK / 16, 256>>>(pAO, proj_down, pT, nullptr);
    dim3 gp(PROJ_NPACK / BNP, M_TOK / BM);  // (6, 784)
    gemm_mma_kernel<1><<<gp, 256, smem>>>(pAO, pWp, proj_b, proj_up, pT, out);
}